// round 15
// baseline (speedup 1.0000x reference)
#include <cuda_runtime.h>
#include <cuda_fp16.h>
#include <stdint.h>

// QINCo: D=128, M=8, K=256, L=2, H=256, BS=1024
namespace {
constexpr int D_  = 128;
constexpr int K_  = 256;
constexpr int M_  = 8;
constexpr int H_  = 256;
constexpr int BS_ = 1024;
constexpr int NR  = BS_ * K_;                   // 262144

constexpr int OUT_CODES = BS_ * D_;             // 131072
constexpr int OUT_SIDE  = OUT_CODES + BS_ * M_; // 139264
constexpr int SIDE_SZ   = BS_ * D_;

constexpr int CH = 10240;                       // one limb chunk: 128 rows * 80B
constexpr int Z0_OFF = 0;
constexpr int H_OFF  = 81920;
constexpr int WS_OFF = 163840;
constexpr int SMEM_F = 204800;

constexpr float TAU   = 1e-2f;
constexpr float INV64 = 1.0f / 64.0f;
}

// ---- device scratch (allocation-free) ----
__device__ __align__(128) float g_cbz[(M_-1) * K_ * D_];
__device__ __align__(128) float g_P1[(M_-1) * K_ * H_];
__device__ __align__(128) float g_Wq1[(M_-1) * H_ * D_];   // W1_0 @ Wx (composite)
__device__ __align__(128) float g_y[BS_ * D_];
__device__ __align__(128) float g_Q1[BS_ * H_];
__device__ __align__(128) float g_xa[BS_ * D_];
__device__ __align__(128) float g_xb[BS_ * D_];
__device__ __align__(128) float g_dist[NR];
// fp16 2-limb weights (pre-scaled x64)
__device__ __align__(128) __half g_w1a[7*32768], g_w1b[7*32768];
__device__ __align__(128) __half g_w2a[14*32768], g_w2b[14*32768];
__device__ int g_code[BS_];

// ================= helpers =================
__device__ __forceinline__ uint32_t smem_u32(const void* p) {
    uint32_t a;
    asm("{ .reg .u64 t; cvta.to.shared.u64 t, %1; cvt.u32.u64 %0, t; }" : "=r"(a) : "l"(p));
    return a;
}
__device__ __forceinline__ void split2(float a, __half& h, __half& l) {
    h = __float2half_rn(a);
    l = __float2half_rn(a - __half2float(h));
}
__device__ __forceinline__ uint32_t pkh(__half a, __half b) {
    return (uint32_t)__half_as_ushort(a) | ((uint32_t)__half_as_ushort(b) << 16);
}
__device__ __forceinline__ void warp_red2(float& a, float& b) {
#pragma unroll
    for (int o = 16; o; o >>= 1) {
        a += __shfl_xor_sync(0xffffffffu, a, o);
        b += __shfl_xor_sync(0xffffffffu, b, o);
    }
}
__device__ __forceinline__ float wred(float a) {
#pragma unroll
    for (int o = 16; o; o >>= 1) a += __shfl_xor_sync(0xffffffffu, a, o);
    return a;
}
__device__ __forceinline__ void mma_f16(float* c, const uint32_t* a, const uint32_t* b) {
    asm volatile("mma.sync.aligned.m16n8k16.row.col.f32.f16.f16.f32 "
        "{%0,%1,%2,%3}, {%4,%5,%6,%7}, {%8,%9}, {%0,%1,%2,%3};"
        : "+f"(c[0]), "+f"(c[1]), "+f"(c[2]), "+f"(c[3])
        : "r"(a[0]), "r"(a[1]), "r"(a[2]), "r"(a[3]), "r"(b[0]), "r"(b[1]));
}
__device__ __forceinline__ void ldm4(uint32_t* r, uint32_t addr) {
    asm volatile("ldmatrix.sync.aligned.m8n8.x4.shared.b16 {%0,%1,%2,%3}, [%4];"
        : "=r"(r[0]), "=r"(r[1]), "=r"(r[2]), "=r"(r[3]) : "r"(addr));
}
__device__ __forceinline__ void cpasync16(uint32_t s, const void* g) {
    asm volatile("cp.async.cg.shared.global [%0], [%1], 16;" :: "r"(s), "l"(g));
}
#define CP_COMMIT() asm volatile("cp.async.commit_group;" ::: "memory")
#define CP_WAIT0()  asm volatile("cp.async.wait_group 0;" ::: "memory")
__device__ __forceinline__ uint64_t dup2(float x) {
    uint64_t r; asm("mov.b64 %0, {%1, %1};" : "=l"(r) : "f"(x)); return r;
}
__device__ __forceinline__ void fma2(uint64_t& d, uint64_t a, uint64_t b) {
    asm("fma.rn.f32x2 %0, %1, %2, %0;" : "+l"(d) : "l"(a), "l"(b));
}
__device__ __forceinline__ float2 u2f(uint64_t v) {
    float2 r; asm("mov.b64 {%0, %1}, %2;" : "=f"(r.x), "=f"(r.y) : "l"(v)); return r;
}

// ================= weight precomputes (once per launch) =================
__global__ void k_splitw(const float* __restrict__ W1, const float* __restrict__ W2) {
    int i = blockIdx.x * 256 + threadIdx.x;
    if (i < 7 * 32768) {
        int mm = i / 32768, r = i % 32768;
        __half h, l;
        split2(64.0f * W1[(mm * 2 + 1) * 32768 + r], h, l);
        g_w1a[i] = h; g_w1b[i] = l;
    }
    if (i < 14 * 32768) {
        __half h, l;
        split2(64.0f * W2[i], h, l);
        g_w2a[i] = h; g_w2b[i] = l;
    }
}
// Wq1[m][h][j] = sum_d W1_0[m][h][d] * Wc[m][d][D+j]
__global__ void k_wq1(const float* __restrict__ Wc, const float* __restrict__ W1) {
    int r = blockIdx.x;          // m*256 + h
    int m = r >> 8, h = r & 255;
    __shared__ float w1row[128];
    int j = threadIdx.x;
    w1row[j] = W1[(m * 2) * 32768 + h * 128 + j];
    __syncthreads();
    float acc = 0.f;
    const float* wc = Wc + m * 32768 + 128 + j;
#pragma unroll 8
    for (int d = 0; d < 128; ++d) acc = fmaf(w1row[d], wc[d * 256], acc);
    g_Wq1[r * 128 + j] = acc;
}

// ================= fused per-step fast path =================
__global__ void __launch_bounds__(256, 1) k_fused(const float* __restrict__ x,
                                                  int m, int ping) {
    extern __shared__ char sm[];
    uint32_t sb = smem_u32(sm);
    const int tid = threadIdx.x, lane = tid & 31, wid = tid >> 5;
    const int wr = (wid >> 2) * 64;
    const int wcn = wid & 3, wc = wcn * 32;
    const int g4 = lane >> 2, q2 = (lane & 3) * 2;
    const int bx = blockIdx.x;
    const int b = bx >> 1, k0 = (bx & 1) * 128;

    float z2[4][4][4] = {};
    float ar[16];

    auto mma_chunk = [&](float acc[4][4][4], uint32_t aB0, uint32_t aB1,
                         uint32_t bB0, uint32_t bB1) {
#pragma unroll
        for (int h16 = 0; h16 < 2; ++h16) {
            const int kb = h16 * 32;
            uint32_t aF[2][4][4], bF[2][4][2];
#pragma unroll
            for (int limb = 0; limb < 2; ++limb) {
                uint32_t aB = limb ? aB1 : aB0;
                uint32_t bB = limb ? bB1 : bB0;
#pragma unroll
                for (int mt = 0; mt < 4; ++mt)
                    ldm4(aF[limb][mt], aB + (wr + mt*16 + (lane & 15))*80 + kb + (lane >> 4)*16);
#pragma unroll
                for (int p = 0; p < 2; ++p) {
                    uint32_t r[4];
                    ldm4(r, bB + (wc + p*16 + (lane & 7) + ((lane >> 4) & 1)*8)*80 + kb + ((lane >> 3) & 1)*16);
                    bF[limb][p*2  ][0] = r[0]; bF[limb][p*2  ][1] = r[1];
                    bF[limb][p*2+1][0] = r[2]; bF[limb][p*2+1][1] = r[3];
                }
            }
#pragma unroll
            for (int mt = 0; mt < 4; ++mt)
#pragma unroll
                for (int nt = 0; nt < 4; ++nt) {
                    mma_f16(acc[mt][nt], aF[0][mt], bF[0][nt]);
                    mma_f16(acc[mt][nt], aF[0][mt], bF[1][nt]);
                    mma_f16(acc[mt][nt], aF[1][mt], bF[0][nt]);
                }
        }
    };
    auto cpW = [&](const __half* Wh, const __half* Wl, int stride, int colOff, int buf) {
#pragma unroll
        for (int limb = 0; limb < 2; ++limb) {
            const __half* src = limb ? Wl : Wh;
#pragma unroll
            for (int i = 0; i < 2; ++i) {
                int r2 = tid + 256*i, row = r2 >> 2, cq = r2 & 3;
                cpasync16(sb + WS_OFF + (buf*2 + limb)*CH + row*80 + cq*16,
                          src + row*stride + colOff + cq*8);
            }
        }
    };
    auto ldgA = [&](int ch) {
#pragma unroll
        for (int i = 0; i < 4; ++i) {
            int idx = tid + 256*i, row = idx >> 3, q = idx & 7;
            int kk = k0 + row;
            float4 p  = *(const float4*)(g_P1 + ((m << 8) + kk)*H_ + ch*32 + q*4);
            float4 qq = *(const float4*)(g_Q1 + b*H_ + ch*32 + q*4);
            ar[i*4+0] = fmaxf(p.x + qq.x, 0.f);
            ar[i*4+1] = fmaxf(p.y + qq.y, 0.f);
            ar[i*4+2] = fmaxf(p.z + qq.z, 0.f);
            ar[i*4+3] = fmaxf(p.w + qq.w, 0.f);
        }
    };
    auto stsA = [&](int buf) {
#pragma unroll
        for (int i = 0; i < 4; ++i) {
            int idx = tid + 256*i, row = idx >> 3, q = idx & 7;
            __half hh[4], ll[4];
#pragma unroll
            for (int j = 0; j < 4; ++j) split2(ar[i*4+j], hh[j], ll[j]);
            char* base = sm + H_OFF + (buf*2)*CH + row*80 + q*8;
            *(uint2*)(base)      = make_uint2(pkh(hh[0],hh[1]), pkh(hh[2],hh[3]));
            *(uint2*)(base + CH) = make_uint2(pkh(ll[0],ll[1]), pkh(ll[2],ll[3]));
        }
    };

    // ---- phase A ----
    {
        float za[4][4][4] = {};
        const __half* WA = g_w2a + 2*m*32768;
        const __half* WB = g_w2b + 2*m*32768;
        ldgA(0);
        cpW(WA, WB, 256, 0, 0);
        CP_COMMIT();
        stsA(0);
        CP_WAIT0();
        __syncthreads();
        int buf = 0;
#pragma unroll 1
        for (int ch = 0; ch < 8; ++ch) {
            if (ch + 1 < 8) {
                ldgA(ch + 1);
                cpW(WA, WB, 256, (ch + 1)*32, buf ^ 1);
                CP_COMMIT();
            }
            mma_chunk(za, sb + H_OFF + (buf*2)*CH, sb + H_OFF + (buf*2+1)*CH,
                          sb + WS_OFF + (buf*2)*CH, sb + WS_OFF + (buf*2+1)*CH);
            if (ch + 1 < 8) {
                stsA(buf ^ 1);
                CP_WAIT0();
                __syncthreads();
                buf ^= 1;
            }
        }
        __syncthreads();
#pragma unroll
        for (int mt = 0; mt < 4; ++mt)
#pragma unroll
            for (int half = 0; half < 2; ++half) {
                int row = wr + mt*16 + g4 + half*8;
#pragma unroll
                for (int nt = 0; nt < 4; ++nt) {
                    int col = wc + nt*8 + q2;
                    float2 cz = *(const float2*)(g_cbz + ((m << 8) + k0 + row)*D_ + col);
                    float2 yy = *(const float2*)(g_y + b*D_ + col);
                    float v0 = za[mt][nt][half*2]   * INV64 + cz.x + yy.x;
                    float v1 = za[mt][nt][half*2+1] * INV64 + cz.y + yy.y;
                    __half h0, l0, h1, l1;
                    split2(v0, h0, l0); split2(v1, h1, l1);
                    uint32_t off = (uint32_t)(((col >> 5)*2)*CH + row*80 + (col & 31)*2);
                    *(uint32_t*)(sm + Z0_OFF + off)      = pkh(h0, h1);
                    *(uint32_t*)(sm + Z0_OFF + off + CH) = pkh(l0, l1);
                }
            }
        __syncthreads();
    }

    // ---- phases B/C per 128-col half ----
#pragma unroll 1
    for (int nh = 0; nh < 2; ++nh) {
        {
            float ha[4][4][4] = {};
            const __half* WA = g_w1a + m*32768 + nh*128*128;
            const __half* WB = g_w1b + m*32768 + nh*128*128;
            cpW(WA, WB, 128, 0, 0);
            CP_COMMIT(); CP_WAIT0(); __syncthreads();
            int buf = 0;
#pragma unroll 1
            for (int ch = 0; ch < 4; ++ch) {
                if (ch + 1 < 4) {
                    cpW(WA, WB, 128, (ch + 1)*32, buf ^ 1);
                    CP_COMMIT();
                }
                mma_chunk(ha, sb + Z0_OFF + (ch*2)*CH, sb + Z0_OFF + (ch*2+1)*CH,
                              sb + WS_OFF + (buf*2)*CH, sb + WS_OFF + (buf*2+1)*CH);
                if (ch + 1 < 4) {
                    CP_WAIT0(); __syncthreads(); buf ^= 1;
                }
            }
            __syncthreads();
#pragma unroll
            for (int mt = 0; mt < 4; ++mt)
#pragma unroll
                for (int half = 0; half < 2; ++half) {
                    int row = wr + mt*16 + g4 + half*8;
#pragma unroll
                    for (int nt = 0; nt < 4; ++nt) {
                        int col = wc + nt*8 + q2;
                        float v0 = fmaxf(ha[mt][nt][half*2]   * INV64, 0.f);
                        float v1 = fmaxf(ha[mt][nt][half*2+1] * INV64, 0.f);
                        __half h0, l0, h1, l1;
                        split2(v0, h0, l0); split2(v1, h1, l1);
                        uint32_t off = (uint32_t)(((col >> 5)*2)*CH + row*80 + (col & 31)*2);
                        *(uint32_t*)(sm + H_OFF + off)      = pkh(h0, h1);
                        *(uint32_t*)(sm + H_OFF + off + CH) = pkh(l0, l1);
                    }
                }
            __syncthreads();
        }
        {
            const __half* WA = g_w2a + (2*m + 1)*32768;
            const __half* WB = g_w2b + (2*m + 1)*32768;
            cpW(WA, WB, 256, nh*128, 0);
            CP_COMMIT(); CP_WAIT0(); __syncthreads();
            int buf = 0;
#pragma unroll 1
            for (int ch = 0; ch < 4; ++ch) {
                if (ch + 1 < 4) {
                    cpW(WA, WB, 256, nh*128 + (ch + 1)*32, buf ^ 1);
                    CP_COMMIT();
                }
                mma_chunk(z2, sb + H_OFF + (ch*2)*CH, sb + H_OFF + (ch*2+1)*CH,
                              sb + WS_OFF + (buf*2)*CH, sb + WS_OFF + (buf*2+1)*CH);
                if (ch + 1 < 4) {
                    CP_WAIT0(); __syncthreads(); buf ^= 1;
                }
            }
            __syncthreads();
        }
    }

    // ---- dist epilogue ----
    const float* xin = ping ? g_xb : g_xa;
    float p8[8];
#pragma unroll
    for (int mt = 0; mt < 4; ++mt)
#pragma unroll
        for (int half = 0; half < 2; ++half) {
            int row = wr + mt*16 + g4 + half*8;
            float p = 0.f;
#pragma unroll
            for (int nt = 0; nt < 4; ++nt) {
                int col = wc + nt*8 + q2;
                uint32_t off = (uint32_t)(((col >> 5)*2)*CH + row*80 + (col & 31)*2);
                uint32_t u0 = *(const uint32_t*)(sm + Z0_OFF + off);
                uint32_t u1 = *(const uint32_t*)(sm + Z0_OFF + off + CH);
                float z0a = __half2float(__ushort_as_half((unsigned short)(u0 & 0xffff)))
                          + __half2float(__ushort_as_half((unsigned short)(u1 & 0xffff)));
                float z0b = __half2float(__ushort_as_half((unsigned short)(u0 >> 16)))
                          + __half2float(__ushort_as_half((unsigned short)(u1 >> 16)));
                float2 xh = *(const float2*)(xin + b*D_ + col);
                float2 xv = *(const float2*)(x + b*D_ + col);
                float zf0 = z0a + z2[mt][nt][half*2]   * INV64 + xh.x;
                float zf1 = z0b + z2[mt][nt][half*2+1] * INV64 + xh.y;
                p += zf0 * (zf0 - 2.f*xv.x) + zf1 * (zf1 - 2.f*xv.y);
            }
            p8[mt*2 + half] = p;
        }
#pragma unroll
    for (int j = 0; j < 8; ++j) {
        p8[j] += __shfl_xor_sync(0xffffffffu, p8[j], 1);
        p8[j] += __shfl_xor_sync(0xffffffffu, p8[j], 2);
    }
    float* sd = (float*)(sm + WS_OFF);
    if ((lane & 3) == 0) {
#pragma unroll
        for (int mt = 0; mt < 4; ++mt)
#pragma unroll
            for (int half = 0; half < 2; ++half)
                sd[(wr + mt*16 + g4 + half*8)*4 + wcn] = p8[mt*2 + half];
    }
    __syncthreads();
    if (tid < 128) {
        float s = sd[tid*4] + sd[tid*4+1] + sd[tid*4+2] + sd[tid*4+3];
        g_dist[bx*128 + tid] = s;
    }
}

// ================= f32x2 exact SGEMM core (setup only, 128-row tiles) ==============
template <int K, int WS>
__device__ __forceinline__ void gemm_acc(const float* __restrict__ A,
                                         const float* __restrict__ W,
                                         float out[8][8],
                                         float (&As)[2][8][128],
                                         float (&Bs)[2][8][128]) {
    const int tid  = threadIdx.x;
    const int cRow = blockIdx.y * 128;
    const int cCol = blockIdx.x * 128;
    const int tRow = (tid >> 4) * 8;
    const int tCol = (tid & 15) * 8;
    const int rA = tid >> 1;
    const int cA = (tid & 1) * 4;

    uint64_t acc2[8][4] = {};
    const float* Ap = A + (cRow + rA) * K + cA;
    const float* Wp = W + (cCol + rA) * WS + cA;

    float4 a4 = *(const float4*)Ap;
    float4 b4 = *(const float4*)Wp;
    As[0][cA+0][rA]=a4.x; As[0][cA+1][rA]=a4.y; As[0][cA+2][rA]=a4.z; As[0][cA+3][rA]=a4.w;
    Bs[0][cA+0][rA]=b4.x; Bs[0][cA+1][rA]=b4.y; Bs[0][cA+2][rA]=b4.z; Bs[0][cA+3][rA]=b4.w;
    __syncthreads();

    constexpr int NT = K / 8;
    int buf = 0;
#pragma unroll 1
    for (int it = 0; it < NT; ++it) {
        float4 an, bn;
        if (it + 1 < NT) {
            an = *(const float4*)(Ap + (it + 1) * 8);
            bn = *(const float4*)(Wp + (it + 1) * 8);
        }
#pragma unroll
        for (int kk = 0; kk < 8; ++kk) {
            float rm[8];
            *(float4*)(rm)   = *(const float4*)&As[buf][kk][tRow];
            *(float4*)(rm+4) = *(const float4*)&As[buf][kk][tRow+4];
            uint64_t rn2[4];
            *(uint4*)(&rn2[0]) = *(const uint4*)&Bs[buf][kk][tCol];
            *(uint4*)(&rn2[2]) = *(const uint4*)&Bs[buf][kk][tCol+4];
#pragma unroll
            for (int i = 0; i < 8; ++i) {
                uint64_t am = dup2(rm[i]);
#pragma unroll
                for (int j = 0; j < 4; ++j) fma2(acc2[i][j], am, rn2[j]);
            }
        }
        if (it + 1 < NT) {
            int nb = buf ^ 1;
            As[nb][cA+0][rA]=an.x; As[nb][cA+1][rA]=an.y; As[nb][cA+2][rA]=an.z; As[nb][cA+3][rA]=an.w;
            Bs[nb][cA+0][rA]=bn.x; Bs[nb][cA+1][rA]=bn.y; Bs[nb][cA+2][rA]=bn.z; Bs[nb][cA+3][rA]=bn.w;
            __syncthreads();
            buf = nb;
        }
    }
#pragma unroll
    for (int i = 0; i < 8; ++i)
#pragma unroll
        for (int j = 0; j < 4; ++j) {
            float2 t = u2f(acc2[i][j]);
            out[i][2*j] = t.x; out[i][2*j+1] = t.y;
        }
}

// ---- setup GEMMs (exact fp32, one-time) ----
__global__ void __launch_bounds__(256) k_cbzg(const float* __restrict__ cbs,
                                              const float* __restrict__ Wc,
                                              const float* __restrict__ bc) {
    __shared__ float As[2][8][128], Bs[2][8][128];
    int m = blockIdx.z;   // grid (1, 2, 7)
    float acc[8][8];
    const float* A = cbs + m * K_ * D_;
    gemm_acc<128, 256>(A, Wc + m * D_ * 2 * D_, acc, As, Bs);
    const int tid = threadIdx.x, cRow = blockIdx.y * 128;
    const int tRow = (tid >> 4) * 8, tCol = (tid & 15) * 8;
#pragma unroll
    for (int i = 0; i < 8; ++i)
#pragma unroll
        for (int j = 0; j < 8; ++j) {
            int r = cRow + tRow + i, c = tCol + j;
            g_cbz[(m * K_ + r) * D_ + c] = acc[i][j] + A[r * D_ + c] + bc[m * D_ + c];
        }
}
__global__ void __launch_bounds__(256) k_p1g(const float* __restrict__ W1) {
    __shared__ float As[2][8][128], Bs[2][8][128];
    int m = blockIdx.z;   // grid (2, 2, 7)
    float acc[8][8];
    gemm_acc<128, 128>(g_cbz + m * K_ * D_, W1 + (m * 2) * H_ * D_, acc, As, Bs);
    const int tid = threadIdx.x, cRow = blockIdx.y * 128, cCol = blockIdx.x * 128;
    const int tRow = (tid >> 4) * 8, tCol = (tid & 15) * 8;
#pragma unroll
    for (int i = 0; i < 8; ++i)
#pragma unroll
        for (int j = 0; j < 8; ++j)
            g_P1[(m * K_ + cRow + tRow + i) * H_ + cCol + tCol + j] = acc[i][j];
}
// initial y / Q1 (step 0), grid (3, 8)
__global__ void __launch_bounds__(256) k_yq0(const float* __restrict__ Wc) {
    __shared__ float As[2][8][128], Bs[2][8][128];
    const int bx = blockIdx.x;
    float acc[8][8];
    const int tid = threadIdx.x, cRow = blockIdx.y * 128;
    const int tRow = (tid >> 4) * 8, tCol = (tid & 15) * 8;
    if (bx == 0) {
        gemm_acc<128, 256>(g_xa, Wc + 128, acc, As, Bs);
#pragma unroll
        for (int i = 0; i < 8; ++i)
#pragma unroll
            for (int j = 0; j < 8; ++j)
                g_y[(cRow + tRow + i) * D_ + tCol + j] = acc[i][j];
    } else {
        gemm_acc<128, 128>(g_xa, g_Wq1 - 16384, acc, As, Bs);   // cCol=bx*128 inside
        const int cCol = (bx - 1) * 128;
#pragma unroll
        for (int i = 0; i < 8; ++i)
#pragma unroll
            for (int j = 0; j < 8; ++j)
                g_Q1[(cRow + tRow + i) * H_ + cCol + tCol + j] = acc[i][j];
    }
}

// ================= step 0 (exact fp32) =================
__global__ void k_step0(const float* __restrict__ x, const float* __restrict__ cb0,
                        float* __restrict__ out) {
    int b = blockIdx.x, t = threadIdx.x;
    int w = t >> 5, lane = t & 31;
    __shared__ float4 xs[32];
    __shared__ float  sd[256];
    __shared__ int    si[256];
    if (t < 32) xs[t] = ((const float4*)x)[b * 32 + t];
    __syncthreads();
    float4 xv = xs[lane];
    for (int i = 0; i < 32; ++i) {
        int k = w * 32 + i;
        float4 c = ((const float4*)cb0)[k * 32 + lane];
        float a1 = c.x*c.x + c.y*c.y + c.z*c.z + c.w*c.w;
        float a2 = xv.x*c.x + xv.y*c.y + xv.z*c.z + xv.w*c.w;
        warp_red2(a1, a2);
        if (lane == 0) sd[k] = a1 - 2.f * a2;
    }
    si[t] = t;
    __syncthreads();
    for (int s = 128; s; s >>= 1) {
        if (t < s) {
            float o = sd[t + s]; int oi = si[t + s];
            if (o < sd[t] || (o == sd[t] && oi < si[t])) { sd[t] = o; si[t] = oi; }
        }
        __syncthreads();
    }
    int kb = si[0];
    if (t < D_) {
        float v = cb0[kb * D_ + t];
        g_xa[b * D_ + t] = v;
        out[OUT_SIDE + b * D_ + t] = v;       // side[0]
    }
    if (t == 0) out[OUT_CODES + b * M_] = (float)kb;
}

// ================= selection + exact rescue (code only) =================
__global__ void k_sel(const float* __restrict__ x, const float* __restrict__ W1,
                      const float* __restrict__ W2, float* __restrict__ out,
                      int m, int ping) {
    int b = blockIdx.x, t = threadIdx.x, lane = t & 31, wid = t >> 5;
    __shared__ float sd[256], sr[256], wk[256];
    __shared__ int   si[256];
    __shared__ int   cnt, clist_s[16];
    __shared__ float xh[128], xv[128], h0s[256], z1s[128], h1s[256], z2s[128];
    __shared__ float red[8], bestd;
    __shared__ int   bestk;

    float d = g_dist[b * 256 + t];
    sd[t] = d; sr[t] = d; si[t] = t;
    if (t == 0) cnt = 0;
    __syncthreads();
    for (int s = 128; s; s >>= 1) {
        if (t < s) {
            float o = sr[t + s]; int oi = si[t + s];
            if (o < sr[t] || (o == sr[t] && oi < si[t])) { sr[t] = o; si[t] = oi; }
        }
        __syncthreads();
    }
    float d1 = sr[0];
    int   kb = si[0];
    if (sd[t] <= d1 + TAU) {
        int pos = atomicAdd(&cnt, 1);
        if (pos < 16) clist_s[pos] = t;
    }
    __syncthreads();
    int C = cnt;
    if (C == 1) {
        if (t == 0) {
            g_code[b] = kb;
            out[OUT_CODES + b * M_ + m + 1] = (float)kb;
        }
        return;
    }
    if (C > 16) {   // extract 16 smallest (rare)
        wk[t] = sd[t];
        __syncthreads();
        for (int r = 0; r < 16; ++r) {
            sr[t] = wk[t]; si[t] = t;
            __syncthreads();
            for (int s = 128; s; s >>= 1) {
                if (t < s) {
                    float o = sr[t + s]; int oi = si[t + s];
                    if (o < sr[t] || (o == sr[t] && oi < si[t])) { sr[t] = o; si[t] = oi; }
                }
                __syncthreads();
            }
            if (t == 0) clist_s[r] = si[0];
            if (t == si[0]) wk[t] = 3.4e38f;
            __syncthreads();
        }
        C = 16;
    }
    const float* xin = ping ? g_xb : g_xa;
    if (t < 128) { xh[t] = xin[b * 128 + t]; xv[t] = x[b * 128 + t]; }
    if (t == 0) { bestd = 3.4e38f; bestk = 0x7fffffff; }
    __syncthreads();
    const float* W2_0 = W2 + (2 * m) * 32768;
    const float* W1_1 = W1 + (2 * m + 1) * 32768;
    const float* W2_1 = W2 + (2 * m + 1) * 32768;
    for (int i = 0; i < C; ++i) {
        int k = clist_s[i];
        h0s[t] = fmaxf(g_P1[(m * K_ + k) * H_ + t] + g_Q1[b * H_ + t], 0.f);
        __syncthreads();
        for (int it = 0; it < 16; ++it) {       // z1
            int dd = it * 8 + wid;
            float a = 0.f;
            const float* wrow = W2_0 + dd * 256;
#pragma unroll
            for (int j = 0; j < 8; ++j) a += wrow[lane + 32*j] * h0s[lane + 32*j];
#pragma unroll
            for (int o = 16; o; o >>= 1) a += __shfl_xor_sync(~0u, a, o);
            if (lane == 0) z1s[dd] = g_cbz[(m * K_ + k) * D_ + dd] + g_y[b * D_ + dd] + a;
        }
        __syncthreads();
        for (int it = 0; it < 32; ++it) {       // h1
            int h = it * 8 + wid;
            float a = 0.f;
            const float* wrow = W1_1 + h * 128;
#pragma unroll
            for (int j = 0; j < 4; ++j) a += wrow[lane + 32*j] * z1s[lane + 32*j];
#pragma unroll
            for (int o = 16; o; o >>= 1) a += __shfl_xor_sync(~0u, a, o);
            if (lane == 0) h1s[h] = fmaxf(a, 0.f);
        }
        __syncthreads();
        for (int it = 0; it < 16; ++it) {       // z2
            int dd = it * 8 + wid;
            float a = 0.f;
            const float* wrow = W2_1 + dd * 256;
#pragma unroll
            for (int j = 0; j < 8; ++j) a += wrow[lane + 32*j] * h1s[lane + 32*j];
#pragma unroll
            for (int o = 16; o; o >>= 1) a += __shfl_xor_sync(~0u, a, o);
            if (lane == 0) z2s[dd] = z1s[dd] + a;
        }
        __syncthreads();
        float p = 0.f;
        if (t < 128) { float zf = z2s[t] + xh[t]; p = zf*zf - 2.f*xv[t]*zf; }
#pragma unroll
        for (int o = 16; o; o >>= 1) p += __shfl_xor_sync(~0u, p, o);
        if (lane == 0) red[wid] = p;
        __syncthreads();
        if (t == 0) {
            float dv = red[0] + red[1] + red[2] + red[3];
            if (dv < bestd || (dv == bestd && k < bestk)) { bestd = dv; bestk = k; }
        }
        __syncthreads();
    }
    if (t == 0) {
        g_code[b] = bestk;
        out[OUT_CODES + b * M_ + m + 1] = (float)bestk;
    }
}

// ================= k_tail: full per-row winner chain + next-step y/Q1 ==============
// grid 128 blocks x 8 warps; one warp per batch row. All data in registers/warp GEMVs.
__global__ void __launch_bounds__(256) k_tail(const float* __restrict__ Wc,
                                              const float* __restrict__ W1,
                                              const float* __restrict__ W2,
                                              float* __restrict__ out,
                                              int m, int ping) {
    const int lane = threadIdx.x & 31, warp = threadIdx.x >> 5;
    const int b = blockIdx.x * 8 + warp;
    const float* xin  = ping ? g_xb : g_xa;
    float*       xout = ping ? g_xa : g_xb;
    const int kb = g_code[b];

    const float* W2_0 = W2 + (2 * m) * 32768;
    const float* W1_1 = W1 + (2 * m + 1) * 32768;
    const float* W2_1 = W2 + (2 * m + 1) * 32768;

    // h0[h] = relu(P1[kb][h] + Q1[b][h]),  h = lane + 32j (owner layout)
    float h0j[8];
#pragma unroll
    for (int j = 0; j < 8; ++j)
        h0j[j] = fmaxf(g_P1[((m << 8) + kb) * H_ + lane + 32*j] + g_Q1[b * H_ + lane + 32*j], 0.f);
    float czy[4], xinj[4];
#pragma unroll
    for (int j = 0; j < 4; ++j) {
        int d = lane + 32*j;
        czy[j]  = g_cbz[((m << 8) + kb) * D_ + d] + g_y[b * D_ + d];
        xinj[j] = xin[b * D_ + d];
    }
    // z1[d] = czy[d] + h0 . W2_0[d]
    float z1j[4];
#pragma unroll 4
    for (int d = 0; d < 128; ++d) {
        const float* wrow = W2_0 + d * 256;
        float a = 0.f;
#pragma unroll
        for (int j = 0; j < 8; ++j) a = fmaf(wrow[lane + 32*j], h0j[j], a);
        a = wred(a);
        if ((d & 31) == lane) z1j[d >> 5] = a + czy[d >> 5];
    }
    // h1[h] = relu(z1 . W1_1[h])
    float h1j[8];
#pragma unroll 4
    for (int h = 0; h < 256; ++h) {
        const float* wrow = W1_1 + h * 128;
        float a = 0.f;
#pragma unroll
        for (int j = 0; j < 4; ++j) a = fmaf(wrow[lane + 32*j], z1j[j], a);
        a = wred(a);
        if ((h & 31) == lane) h1j[h >> 5] = fmaxf(a, 0.f);
    }
    // xhat[d] = z1[d] + h1 . W2_1[d] + xin[d]
    float xhj[4];
#pragma unroll 4
    for (int d = 0; d < 128; ++d) {
        const float* wrow = W2_1 + d * 256;
        float a = 0.f;
#pragma unroll
        for (int j = 0; j < 8; ++j) a = fmaf(wrow[lane + 32*j], h1j[j], a);
        a = wred(a);
        if ((d & 31) == lane) xhj[d >> 5] = a + z1j[d >> 5] + xinj[d >> 5];
    }
    // emit xhat, side, (final)
#pragma unroll
    for (int j = 0; j < 4; ++j) {
        int d = lane + 32*j;
        float v = xhj[j];
        xout[b * D_ + d] = v;
        out[OUT_SIDE + (m + 1) * SIDE_SZ + b * D_ + d] = v;
        if (m == M_ - 2) out[b * D_ + d] = v;
    }
    if (m < M_ - 2) {
        int mn = m + 1;
        // y_next[d] = sum_k xhat[k] * Wx[d][k],  Wx[d][k] = Wc[mn][d][128+k] (contiguous in k)
        float yn[4];
#pragma unroll 4
        for (int d = 0; d < 128; ++d) {
            const float* wrow = Wc + mn * 32768 + d * 256 + 128;
            float a = 0.f;
#pragma unroll
            for (int j = 0; j < 4; ++j) a = fmaf(wrow[lane + 32*j], xhj[j], a);
            a = wred(a);
            if ((d & 31) == lane) yn[d >> 5] = a;
        }
        // Q1_next[h] = xhat . Wq1[mn][h]
        float qn[8];
#pragma unroll 4
        for (int h = 0; h < 256; ++h) {
            const float* wrow = g_Wq1 + (mn * 256 + h) * 128;
            float a = 0.f;
#pragma unroll
            for (int j = 0; j < 4; ++j) a = fmaf(wrow[lane + 32*j], xhj[j], a);
            a = wred(a);
            if ((h & 31) == lane) qn[h >> 5] = a;
        }
#pragma unroll
        for (int j = 0; j < 4; ++j) g_y[b * D_ + lane + 32*j] = yn[j];
#pragma unroll
        for (int j = 0; j < 8; ++j) g_Q1[b * H_ + lane + 32*j] = qn[j];
    }
}

extern "C" void kernel_launch(void* const* d_in, const int* in_sizes, int n_in,
                              void* d_out, int out_size) {
    const float* x   = (const float*)d_in[0];
    const float* cb0 = (const float*)d_in[1];
    const float* cbs = (const float*)d_in[2];
    const float* Wc  = (const float*)d_in[3];
    const float* bc  = (const float*)d_in[4];
    const float* W1  = (const float*)d_in[5];
    const float* W2  = (const float*)d_in[6];
    float* out = (float*)d_out;

    cudaFuncSetAttribute(k_fused, cudaFuncAttributeMaxDynamicSharedMemorySize, SMEM_F);

    // weight-only precomputes
    k_splitw<<<1792, 256>>>(W1, W2);
    k_wq1<<<(M_ - 1) * K_, 128>>>(Wc, W1);
    k_cbzg<<<dim3(1, 2, 7), 256>>>(cbs, Wc, bc);
    k_p1g<<<dim3(2, 2, 7), 256>>>(W1);
    k_step0<<<BS_, 256>>>(x, cb0, out);
    k_yq0<<<dim3(3, 8), 256>>>(Wc);        // initial y/Q1 (xhat in g_xa)

    int ping = 0;   // xhat currently in (ping ? g_xb : g_xa)
    for (int m = 0; m < M_ - 1; ++m) {
        k_fused<<<2048, 256, SMEM_F>>>(x, m, ping);
        k_sel<<<BS_, 256>>>(x, W1, W2, out, m, ping);
        k_tail<<<128, 256>>>(Wc, W1, W2, out, m, ping);
        ping ^= 1;
    }
}

// round 16
// speedup vs baseline: 1.2056x; 1.2056x over previous
#include <cuda_runtime.h>
#include <cuda_fp16.h>
#include <stdint.h>

// QINCo: D=128, M=8, K=256, L=2, H=256, BS=1024
namespace {
constexpr int D_  = 128;
constexpr int K_  = 256;
constexpr int M_  = 8;
constexpr int H_  = 256;
constexpr int BS_ = 1024;
constexpr int NR  = BS_ * K_;                   // 262144

constexpr int OUT_CODES = BS_ * D_;             // 131072
constexpr int OUT_SIDE  = OUT_CODES + BS_ * M_; // 139264
constexpr int SIDE_SZ   = BS_ * D_;

constexpr int CH = 10240;                       // one limb chunk: 128 rows * 80B
constexpr int Z0_OFF = 0;
constexpr int H_OFF  = 81920;
constexpr int WS_OFF = 163840;
constexpr int SMEM_F = 204800;

constexpr float TAU   = 1e-2f;
constexpr float INV64 = 1.0f / 64.0f;
}

// ---- device scratch (allocation-free) ----
__device__ __align__(128) float g_cbz[(M_-1) * K_ * D_];
__device__ __align__(128) float g_P1[(M_-1) * K_ * H_];
__device__ __align__(128) float g_Wq1[(M_-1) * H_ * D_];   // W1_0 @ Wx (composite)
__device__ __align__(128) float g_y[BS_ * D_];
__device__ __align__(128) float g_Q1[BS_ * H_];
__device__ __align__(128) float g_xa[BS_ * D_];
__device__ __align__(128) float g_xb[BS_ * D_];
__device__ __align__(128) float g_dist[NR];
// fp16 2-limb weights (pre-scaled x64)
__device__ __align__(128) __half g_w1a[7*32768], g_w1b[7*32768];
__device__ __align__(128) __half g_w2a[14*32768], g_w2b[14*32768];
// winner machinery
__device__ __align__(128) float g_h0w[BS_ * H_];
__device__ __align__(128) float g_z1w[BS_ * D_];
__device__ __align__(128) float g_h1w[BS_ * H_];
__device__ int g_code[BS_];

// ================= helpers =================
__device__ __forceinline__ uint32_t smem_u32(const void* p) {
    uint32_t a;
    asm("{ .reg .u64 t; cvta.to.shared.u64 t, %1; cvt.u32.u64 %0, t; }" : "=r"(a) : "l"(p));
    return a;
}
__device__ __forceinline__ void split2(float a, __half& h, __half& l) {
    h = __float2half_rn(a);
    l = __float2half_rn(a - __half2float(h));
}
__device__ __forceinline__ uint32_t pkh(__half a, __half b) {
    return (uint32_t)__half_as_ushort(a) | ((uint32_t)__half_as_ushort(b) << 16);
}
__device__ __forceinline__ void warp_red2(float& a, float& b) {
#pragma unroll
    for (int o = 16; o; o >>= 1) {
        a += __shfl_xor_sync(0xffffffffu, a, o);
        b += __shfl_xor_sync(0xffffffffu, b, o);
    }
}
__device__ __forceinline__ void mma_f16(float* c, const uint32_t* a, const uint32_t* b) {
    asm volatile("mma.sync.aligned.m16n8k16.row.col.f32.f16.f16.f32 "
        "{%0,%1,%2,%3}, {%4,%5,%6,%7}, {%8,%9}, {%0,%1,%2,%3};"
        : "+f"(c[0]), "+f"(c[1]), "+f"(c[2]), "+f"(c[3])
        : "r"(a[0]), "r"(a[1]), "r"(a[2]), "r"(a[3]), "r"(b[0]), "r"(b[1]));
}
__device__ __forceinline__ void ldm4(uint32_t* r, uint32_t addr) {
    asm volatile("ldmatrix.sync.aligned.m8n8.x4.shared.b16 {%0,%1,%2,%3}, [%4];"
        : "=r"(r[0]), "=r"(r[1]), "=r"(r[2]), "=r"(r[3]) : "r"(addr));
}
__device__ __forceinline__ void cpasync16(uint32_t s, const void* g) {
    asm volatile("cp.async.cg.shared.global [%0], [%1], 16;" :: "r"(s), "l"(g));
}
#define CP_COMMIT() asm volatile("cp.async.commit_group;" ::: "memory")
#define CP_WAIT0()  asm volatile("cp.async.wait_group 0;" ::: "memory")
__device__ __forceinline__ uint64_t dup2(float x) {
    uint64_t r; asm("mov.b64 %0, {%1, %1};" : "=l"(r) : "f"(x)); return r;
}
__device__ __forceinline__ void fma2(uint64_t& d, uint64_t a, uint64_t b) {
    asm("fma.rn.f32x2 %0, %1, %2, %0;" : "+l"(d) : "l"(a), "l"(b));
}
__device__ __forceinline__ float2 u2f(uint64_t v) {
    float2 r; asm("mov.b64 {%0, %1}, %2;" : "=f"(r.x), "=f"(r.y) : "l"(v)); return r;
}

// ================= weight precomputes (once per launch) =================
__global__ void k_splitw(const float* __restrict__ W1, const float* __restrict__ W2) {
    int i = blockIdx.x * 256 + threadIdx.x;
    if (i < 7 * 32768) {
        int mm = i / 32768, r = i % 32768;
        __half h, l;
        split2(64.0f * W1[(mm * 2 + 1) * 32768 + r], h, l);
        g_w1a[i] = h; g_w1b[i] = l;
    }
    if (i < 14 * 32768) {
        __half h, l;
        split2(64.0f * W2[i], h, l);
        g_w2a[i] = h; g_w2b[i] = l;
    }
}
// Wq1[m][h][j] = sum_d W1_0[m][h][d] * Wc[m][d][D+j]
__global__ void k_wq1(const float* __restrict__ Wc, const float* __restrict__ W1) {
    int r = blockIdx.x;          // m*256 + h
    int m = r >> 8, h = r & 255;
    __shared__ float w1row[128];
    int j = threadIdx.x;
    w1row[j] = W1[(m * 2) * 32768 + h * 128 + j];
    __syncthreads();
    float acc = 0.f;
    const float* wc = Wc + m * 32768 + 128 + j;
#pragma unroll 8
    for (int d = 0; d < 128; ++d) acc = fmaf(w1row[d], wc[d * 256], acc);
    g_Wq1[r * 128 + j] = acc;
}

// ================= fused per-step fast path (R11/R13 version) =================
__global__ void __launch_bounds__(256, 1) k_fused(const float* __restrict__ x,
                                                  int m, int ping) {
    extern __shared__ char sm[];
    uint32_t sb = smem_u32(sm);
    const int tid = threadIdx.x, lane = tid & 31, wid = tid >> 5;
    const int wr = (wid >> 2) * 64;
    const int wcn = wid & 3, wc = wcn * 32;
    const int g4 = lane >> 2, q2 = (lane & 3) * 2;
    const int bx = blockIdx.x;
    const int b = bx >> 1, k0 = (bx & 1) * 128;

    float z2[4][4][4] = {};
    float ar[16];

    auto mma_chunk = [&](float acc[4][4][4], uint32_t aB0, uint32_t aB1,
                         uint32_t bB0, uint32_t bB1) {
#pragma unroll
        for (int h16 = 0; h16 < 2; ++h16) {
            const int kb = h16 * 32;
            uint32_t aF[2][4][4], bF[2][4][2];
#pragma unroll
            for (int limb = 0; limb < 2; ++limb) {
                uint32_t aB = limb ? aB1 : aB0;
                uint32_t bB = limb ? bB1 : bB0;
#pragma unroll
                for (int mt = 0; mt < 4; ++mt)
                    ldm4(aF[limb][mt], aB + (wr + mt*16 + (lane & 15))*80 + kb + (lane >> 4)*16);
#pragma unroll
                for (int p = 0; p < 2; ++p) {
                    uint32_t r[4];
                    ldm4(r, bB + (wc + p*16 + (lane & 7) + ((lane >> 4) & 1)*8)*80 + kb + ((lane >> 3) & 1)*16);
                    bF[limb][p*2  ][0] = r[0]; bF[limb][p*2  ][1] = r[1];
                    bF[limb][p*2+1][0] = r[2]; bF[limb][p*2+1][1] = r[3];
                }
            }
#pragma unroll
            for (int mt = 0; mt < 4; ++mt)
#pragma unroll
                for (int nt = 0; nt < 4; ++nt) {
                    mma_f16(acc[mt][nt], aF[0][mt], bF[0][nt]);
                    mma_f16(acc[mt][nt], aF[0][mt], bF[1][nt]);
                    mma_f16(acc[mt][nt], aF[1][mt], bF[0][nt]);
                }
        }
    };
    auto cpW = [&](const __half* Wh, const __half* Wl, int stride, int colOff, int buf) {
#pragma unroll
        for (int limb = 0; limb < 2; ++limb) {
            const __half* src = limb ? Wl : Wh;
#pragma unroll
            for (int i = 0; i < 2; ++i) {
                int r2 = tid + 256*i, row = r2 >> 2, cq = r2 & 3;
                cpasync16(sb + WS_OFF + (buf*2 + limb)*CH + row*80 + cq*16,
                          src + row*stride + colOff + cq*8);
            }
        }
    };
    auto ldgA = [&](int ch) {
#pragma unroll
        for (int i = 0; i < 4; ++i) {
            int idx = tid + 256*i, row = idx >> 3, q = idx & 7;
            int kk = k0 + row;
            float4 p  = *(const float4*)(g_P1 + ((m << 8) + kk)*H_ + ch*32 + q*4);
            float4 qq = *(const float4*)(g_Q1 + b*H_ + ch*32 + q*4);
            ar[i*4+0] = fmaxf(p.x + qq.x, 0.f);
            ar[i*4+1] = fmaxf(p.y + qq.y, 0.f);
            ar[i*4+2] = fmaxf(p.z + qq.z, 0.f);
            ar[i*4+3] = fmaxf(p.w + qq.w, 0.f);
        }
    };
    auto stsA = [&](int buf) {
#pragma unroll
        for (int i = 0; i < 4; ++i) {
            int idx = tid + 256*i, row = idx >> 3, q = idx & 7;
            __half hh[4], ll[4];
#pragma unroll
            for (int j = 0; j < 4; ++j) split2(ar[i*4+j], hh[j], ll[j]);
            char* base = sm + H_OFF + (buf*2)*CH + row*80 + q*8;
            *(uint2*)(base)      = make_uint2(pkh(hh[0],hh[1]), pkh(hh[2],hh[3]));
            *(uint2*)(base + CH) = make_uint2(pkh(ll[0],ll[1]), pkh(ll[2],ll[3]));
        }
    };

    // ---- phase A ----
    {
        float za[4][4][4] = {};
        const __half* WA = g_w2a + 2*m*32768;
        const __half* WB = g_w2b + 2*m*32768;
        ldgA(0);
        cpW(WA, WB, 256, 0, 0);
        CP_COMMIT();
        stsA(0);
        CP_WAIT0();
        __syncthreads();
        int buf = 0;
#pragma unroll 1
        for (int ch = 0; ch < 8; ++ch) {
            if (ch + 1 < 8) {
                ldgA(ch + 1);
                cpW(WA, WB, 256, (ch + 1)*32, buf ^ 1);
                CP_COMMIT();
            }
            mma_chunk(za, sb + H_OFF + (buf*2)*CH, sb + H_OFF + (buf*2+1)*CH,
                          sb + WS_OFF + (buf*2)*CH, sb + WS_OFF + (buf*2+1)*CH);
            if (ch + 1 < 8) {
                stsA(buf ^ 1);
                CP_WAIT0();
                __syncthreads();
                buf ^= 1;
            }
        }
        __syncthreads();
#pragma unroll
        for (int mt = 0; mt < 4; ++mt)
#pragma unroll
            for (int half = 0; half < 2; ++half) {
                int row = wr + mt*16 + g4 + half*8;
#pragma unroll
                for (int nt = 0; nt < 4; ++nt) {
                    int col = wc + nt*8 + q2;
                    float2 cz = *(const float2*)(g_cbz + ((m << 8) + k0 + row)*D_ + col);
                    float2 yy = *(const float2*)(g_y + b*D_ + col);
                    float v0 = za[mt][nt][half*2]   * INV64 + cz.x + yy.x;
                    float v1 = za[mt][nt][half*2+1] * INV64 + cz.y + yy.y;
                    __half h0, l0, h1, l1;
                    split2(v0, h0, l0); split2(v1, h1, l1);
                    uint32_t off = (uint32_t)(((col >> 5)*2)*CH + row*80 + (col & 31)*2);
                    *(uint32_t*)(sm + Z0_OFF + off)      = pkh(h0, h1);
                    *(uint32_t*)(sm + Z0_OFF + off + CH) = pkh(l0, l1);
                }
            }
        __syncthreads();
    }

    // ---- phases B/C per 128-col half ----
#pragma unroll 1
    for (int nh = 0; nh < 2; ++nh) {
        {
            float ha[4][4][4] = {};
            const __half* WA = g_w1a + m*32768 + nh*128*128;
            const __half* WB = g_w1b + m*32768 + nh*128*128;
            cpW(WA, WB, 128, 0, 0);
            CP_COMMIT(); CP_WAIT0(); __syncthreads();
            int buf = 0;
#pragma unroll 1
            for (int ch = 0; ch < 4; ++ch) {
                if (ch + 1 < 4) {
                    cpW(WA, WB, 128, (ch + 1)*32, buf ^ 1);
                    CP_COMMIT();
                }
                mma_chunk(ha, sb + Z0_OFF + (ch*2)*CH, sb + Z0_OFF + (ch*2+1)*CH,
                              sb + WS_OFF + (buf*2)*CH, sb + WS_OFF + (buf*2+1)*CH);
                if (ch + 1 < 4) {
                    CP_WAIT0(); __syncthreads(); buf ^= 1;
                }
            }
            __syncthreads();
#pragma unroll
            for (int mt = 0; mt < 4; ++mt)
#pragma unroll
                for (int half = 0; half < 2; ++half) {
                    int row = wr + mt*16 + g4 + half*8;
#pragma unroll
                    for (int nt = 0; nt < 4; ++nt) {
                        int col = wc + nt*8 + q2;
                        float v0 = fmaxf(ha[mt][nt][half*2]   * INV64, 0.f);
                        float v1 = fmaxf(ha[mt][nt][half*2+1] * INV64, 0.f);
                        __half h0, l0, h1, l1;
                        split2(v0, h0, l0); split2(v1, h1, l1);
                        uint32_t off = (uint32_t)(((col >> 5)*2)*CH + row*80 + (col & 31)*2);
                        *(uint32_t*)(sm + H_OFF + off)      = pkh(h0, h1);
                        *(uint32_t*)(sm + H_OFF + off + CH) = pkh(l0, l1);
                    }
                }
            __syncthreads();
        }
        {
            const __half* WA = g_w2a + (2*m + 1)*32768;
            const __half* WB = g_w2b + (2*m + 1)*32768;
            cpW(WA, WB, 256, nh*128, 0);
            CP_COMMIT(); CP_WAIT0(); __syncthreads();
            int buf = 0;
#pragma unroll 1
            for (int ch = 0; ch < 4; ++ch) {
                if (ch + 1 < 4) {
                    cpW(WA, WB, 256, nh*128 + (ch + 1)*32, buf ^ 1);
                    CP_COMMIT();
                }
                mma_chunk(z2, sb + H_OFF + (ch*2)*CH, sb + H_OFF + (ch*2+1)*CH,
                              sb + WS_OFF + (buf*2)*CH, sb + WS_OFF + (buf*2+1)*CH);
                if (ch + 1 < 4) {
                    CP_WAIT0(); __syncthreads(); buf ^= 1;
                }
            }
            __syncthreads();
        }
    }

    // ---- dist epilogue ----
    const float* xin = ping ? g_xb : g_xa;
    float p8[8];
#pragma unroll
    for (int mt = 0; mt < 4; ++mt)
#pragma unroll
        for (int half = 0; half < 2; ++half) {
            int row = wr + mt*16 + g4 + half*8;
            float p = 0.f;
#pragma unroll
            for (int nt = 0; nt < 4; ++nt) {
                int col = wc + nt*8 + q2;
                uint32_t off = (uint32_t)(((col >> 5)*2)*CH + row*80 + (col & 31)*2);
                uint32_t u0 = *(const uint32_t*)(sm + Z0_OFF + off);
                uint32_t u1 = *(const uint32_t*)(sm + Z0_OFF + off + CH);
                float z0a = __half2float(__ushort_as_half((unsigned short)(u0 & 0xffff)))
                          + __half2float(__ushort_as_half((unsigned short)(u1 & 0xffff)));
                float z0b = __half2float(__ushort_as_half((unsigned short)(u0 >> 16)))
                          + __half2float(__ushort_as_half((unsigned short)(u1 >> 16)));
                float2 xh = *(const float2*)(xin + b*D_ + col);
                float2 xv = *(const float2*)(x + b*D_ + col);
                float zf0 = z0a + z2[mt][nt][half*2]   * INV64 + xh.x;
                float zf1 = z0b + z2[mt][nt][half*2+1] * INV64 + xh.y;
                p += zf0 * (zf0 - 2.f*xv.x) + zf1 * (zf1 - 2.f*xv.y);
            }
            p8[mt*2 + half] = p;
        }
#pragma unroll
    for (int j = 0; j < 8; ++j) {
        p8[j] += __shfl_xor_sync(0xffffffffu, p8[j], 1);
        p8[j] += __shfl_xor_sync(0xffffffffu, p8[j], 2);
    }
    float* sd = (float*)(sm + WS_OFF);
    if ((lane & 3) == 0) {
#pragma unroll
        for (int mt = 0; mt < 4; ++mt)
#pragma unroll
            for (int half = 0; half < 2; ++half)
                sd[(wr + mt*16 + g4 + half*8)*4 + wcn] = p8[mt*2 + half];
    }
    __syncthreads();
    if (tid < 128) {
        float s = sd[tid*4] + sd[tid*4+1] + sd[tid*4+2] + sd[tid*4+3];
        g_dist[bx*128 + tid] = s;
    }
}

// ================= f32x2 exact SGEMM core, templated on tile rows ==================
template <int ROWS, int K, int WS>
__device__ __forceinline__ void gemm_accR(const float* __restrict__ A,
                                          const float* __restrict__ W,
                                          float out[8][8],
                                          float (&As)[2][8][ROWS],
                                          float (&Bs)[2][8][128]) {
    constexpr int MR = ROWS / 16;                 // 8 or 4 micro rows
    const int tid  = threadIdx.x;
    const int cRow = blockIdx.y * ROWS;
    const int cCol = blockIdx.x * 128;
    const int tRow = (tid >> 4) * MR;
    const int tCol = (tid & 15) * 8;
    const int rA = tid >> 1;
    const int cA = (tid & 1) * 4;
    const bool aAct = (ROWS == 128) || (tid < ROWS * 2);

    uint64_t acc2[8][4] = {};
    const float* Ap = A + (cRow + (aAct ? rA : 0)) * K + cA;
    const float* Wp = W + (cCol + rA) * WS + cA;

    float4 a4 = make_float4(0.f, 0.f, 0.f, 0.f);
    if (aAct) a4 = *(const float4*)Ap;
    float4 b4 = *(const float4*)Wp;
    if (aAct) {
        As[0][cA+0][rA]=a4.x; As[0][cA+1][rA]=a4.y; As[0][cA+2][rA]=a4.z; As[0][cA+3][rA]=a4.w;
    }
    Bs[0][cA+0][rA]=b4.x; Bs[0][cA+1][rA]=b4.y; Bs[0][cA+2][rA]=b4.z; Bs[0][cA+3][rA]=b4.w;
    __syncthreads();

    constexpr int NT = K / 8;
    int buf = 0;
#pragma unroll 1
    for (int it = 0; it < NT; ++it) {
        float4 an = make_float4(0.f, 0.f, 0.f, 0.f), bn;
        if (it + 1 < NT) {
            if (aAct) an = *(const float4*)(Ap + (it + 1) * 8);
            bn = *(const float4*)(Wp + (it + 1) * 8);
        }
#pragma unroll
        for (int kk = 0; kk < 8; ++kk) {
            float rm[MR];
#pragma unroll
            for (int r = 0; r < MR; r += 4)
                *(float4*)(rm + r) = *(const float4*)&As[buf][kk][tRow + r];
            uint64_t rn2[4];
            *(uint4*)(&rn2[0]) = *(const uint4*)&Bs[buf][kk][tCol];
            *(uint4*)(&rn2[2]) = *(const uint4*)&Bs[buf][kk][tCol+4];
#pragma unroll
            for (int i = 0; i < MR; ++i) {
                uint64_t am = dup2(rm[i]);
#pragma unroll
                for (int j = 0; j < 4; ++j) fma2(acc2[i][j], am, rn2[j]);
            }
        }
        if (it + 1 < NT) {
            int nb = buf ^ 1;
            if (aAct) {
                As[nb][cA+0][rA]=an.x; As[nb][cA+1][rA]=an.y; As[nb][cA+2][rA]=an.z; As[nb][cA+3][rA]=an.w;
            }
            Bs[nb][cA+0][rA]=bn.x; Bs[nb][cA+1][rA]=bn.y; Bs[nb][cA+2][rA]=bn.z; Bs[nb][cA+3][rA]=bn.w;
            __syncthreads();
            buf = nb;
        }
    }
#pragma unroll
    for (int i = 0; i < MR; ++i)
#pragma unroll
        for (int j = 0; j < 4; ++j) {
            float2 t = u2f(acc2[i][j]);
            out[i][2*j] = t.x; out[i][2*j+1] = t.y;
        }
}

// ---- setup GEMMs (exact fp32, 128-row tiles, one-time) ----
__global__ void __launch_bounds__(256) k_cbzg(const float* __restrict__ cbs,
                                              const float* __restrict__ Wc,
                                              const float* __restrict__ bc) {
    __shared__ float As[2][8][128], Bs[2][8][128];
    int m = blockIdx.z;   // grid (1, 2, 7)
    float acc[8][8];
    const float* A = cbs + m * K_ * D_;
    gemm_accR<128, 128, 256>(A, Wc + m * D_ * 2 * D_, acc, As, Bs);
    const int tid = threadIdx.x, cRow = blockIdx.y * 128;
    const int tRow = (tid >> 4) * 8, tCol = (tid & 15) * 8;
#pragma unroll
    for (int i = 0; i < 8; ++i)
#pragma unroll
        for (int j = 0; j < 8; ++j) {
            int r = cRow + tRow + i, c = tCol + j;
            g_cbz[(m * K_ + r) * D_ + c] = acc[i][j] + A[r * D_ + c] + bc[m * D_ + c];
        }
}
__global__ void __launch_bounds__(256) k_p1g(const float* __restrict__ W1) {
    __shared__ float As[2][8][128], Bs[2][8][128];
    int m = blockIdx.z;   // grid (2, 2, 7)
    float acc[8][8];
    gemm_accR<128, 128, 128>(g_cbz + m * K_ * D_, W1 + (m * 2) * H_ * D_, acc, As, Bs);
    const int tid = threadIdx.x, cRow = blockIdx.y * 128, cCol = blockIdx.x * 128;
    const int tRow = (tid >> 4) * 8, tCol = (tid & 15) * 8;
#pragma unroll
    for (int i = 0; i < 8; ++i)
#pragma unroll
        for (int j = 0; j < 8; ++j)
            g_P1[(m * K_ + cRow + tRow + i) * H_ + cCol + tCol + j] = acc[i][j];
}
// initial y AND Q1 (step 0), 64-row tiles, grid (3, 16)
__global__ void __launch_bounds__(256) k_yq(const float* __restrict__ Wc, int mn, int ping) {
    __shared__ float As[2][8][64], Bs[2][8][128];
    const float* src = ping ? g_xb : g_xa;
    const int bx = blockIdx.x;
    float acc[8][8];
    const int tid = threadIdx.x, cRow = blockIdx.y * 64;
    const int tRow = (tid >> 4) * 4, tCol = (tid & 15) * 8;
    if (bx == 0) {
        gemm_accR<64, 128, 256>(src, Wc + mn * 32768 + 128, acc, As, Bs);
#pragma unroll
        for (int i = 0; i < 4; ++i)
#pragma unroll
            for (int j = 0; j < 8; ++j)
                g_y[(cRow + tRow + i) * D_ + tCol + j] = acc[i][j];
    } else {
        gemm_accR<64, 128, 128>(src, g_Wq1 + mn * 32768 - 16384, acc, As, Bs);
        const int cCol = (bx - 1) * 128;
#pragma unroll
        for (int i = 0; i < 4; ++i)
#pragma unroll
            for (int j = 0; j < 8; ++j)
                g_Q1[(cRow + tRow + i) * H_ + cCol + tCol + j] = acc[i][j];
    }
}

// ================= step 0 (exact fp32) =================
__global__ void k_step0(const float* __restrict__ x, const float* __restrict__ cb0,
                        float* __restrict__ out) {
    int b = blockIdx.x, t = threadIdx.x;
    int w = t >> 5, lane = t & 31;
    __shared__ float4 xs[32];
    __shared__ float  sd[256];
    __shared__ int    si[256];
    if (t < 32) xs[t] = ((const float4*)x)[b * 32 + t];
    __syncthreads();
    float4 xv = xs[lane];
    for (int i = 0; i < 32; ++i) {
        int k = w * 32 + i;
        float4 c = ((const float4*)cb0)[k * 32 + lane];
        float a1 = c.x*c.x + c.y*c.y + c.z*c.z + c.w*c.w;
        float a2 = xv.x*c.x + xv.y*c.y + xv.z*c.z + xv.w*c.w;
        warp_red2(a1, a2);
        if (lane == 0) sd[k] = a1 - 2.f * a2;
    }
    si[t] = t;
    __syncthreads();
    for (int s = 128; s; s >>= 1) {
        if (t < s) {
            float o = sd[t + s]; int oi = si[t + s];
            if (o < sd[t] || (o == sd[t] && oi < si[t])) { sd[t] = o; si[t] = oi; }
        }
        __syncthreads();
    }
    int kb = si[0];
    if (t < D_) {
        float v = cb0[kb * D_ + t];
        g_xa[b * D_ + t] = v;
        out[OUT_SIDE + b * D_ + t] = v;       // side[0]
    }
    if (t == 0) out[OUT_CODES + b * M_] = (float)kb;
}

// ================= merged selection + exact rescue + h0 emit =================
__global__ void k_sel(const float* __restrict__ x, const float* __restrict__ W1,
                      const float* __restrict__ W2, float* __restrict__ out,
                      int m, int ping) {
    int b = blockIdx.x, t = threadIdx.x, lane = t & 31, wid = t >> 5;
    __shared__ float sd[256], sr[256], wk[256];
    __shared__ int   si[256];
    __shared__ int   cnt, clist_s[16];
    __shared__ float xh[128], xv[128], h0s[256], z1s[128], h1s[256], z2s[128];
    __shared__ float red[8], bestd;
    __shared__ int   bestk;

    float d = g_dist[b * 256 + t];
    sd[t] = d; sr[t] = d; si[t] = t;
    if (t == 0) cnt = 0;
    __syncthreads();
    for (int s = 128; s; s >>= 1) {
        if (t < s) {
            float o = sr[t + s]; int oi = si[t + s];
            if (o < sr[t] || (o == sr[t] && oi < si[t])) { sr[t] = o; si[t] = oi; }
        }
        __syncthreads();
    }
    float d1 = sr[0];
    int   kb = si[0];
    if (sd[t] <= d1 + TAU) {
        int pos = atomicAdd(&cnt, 1);
        if (pos < 16) clist_s[pos] = t;
    }
    __syncthreads();
    int C = cnt;
    if (C == 1) {
        if (t == 0) {
            g_code[b] = kb;
            out[OUT_CODES + b * M_ + m + 1] = (float)kb;
        }
        g_h0w[b * H_ + t] = fmaxf(g_P1[((m << 8) + kb) * H_ + t] + g_Q1[b * H_ + t], 0.f);
        return;
    }
    if (C > 16) {   // extract 16 smallest (rare)
        wk[t] = sd[t];
        __syncthreads();
        for (int r = 0; r < 16; ++r) {
            sr[t] = wk[t]; si[t] = t;
            __syncthreads();
            for (int s = 128; s; s >>= 1) {
                if (t < s) {
                    float o = sr[t + s]; int oi = si[t + s];
                    if (o < sr[t] || (o == sr[t] && oi < si[t])) { sr[t] = o; si[t] = oi; }
                }
                __syncthreads();
            }
            if (t == 0) clist_s[r] = si[0];
            if (t == si[0]) wk[t] = 3.4e38f;
            __syncthreads();
        }
        C = 16;
    }
    const float* xin = ping ? g_xb : g_xa;
    if (t < 128) { xh[t] = xin[b * 128 + t]; xv[t] = x[b * 128 + t]; }
    if (t == 0) { bestd = 3.4e38f; bestk = 0x7fffffff; }
    __syncthreads();
    const float* W2_0 = W2 + (2 * m) * 32768;
    const float* W1_1 = W1 + (2 * m + 1) * 32768;
    const float* W2_1 = W2 + (2 * m + 1) * 32768;
    for (int i = 0; i < C; ++i) {
        int k = clist_s[i];
        h0s[t] = fmaxf(g_P1[(m * K_ + k) * H_ + t] + g_Q1[b * H_ + t], 0.f);
        __syncthreads();
        for (int it = 0; it < 16; ++it) {       // z1
            int dd = it * 8 + wid;
            float a = 0.f;
            const float* wrow = W2_0 + dd * 256;
#pragma unroll
            for (int j = 0; j < 8; ++j) a += wrow[lane + 32*j] * h0s[lane + 32*j];
#pragma unroll
            for (int o = 16; o; o >>= 1) a += __shfl_xor_sync(~0u, a, o);
            if (lane == 0) z1s[dd] = g_cbz[(m * K_ + k) * D_ + dd] + g_y[b * D_ + dd] + a;
        }
        __syncthreads();
        for (int it = 0; it < 32; ++it) {       // h1
            int h = it * 8 + wid;
            float a = 0.f;
            const float* wrow = W1_1 + h * 128;
#pragma unroll
            for (int j = 0; j < 4; ++j) a += wrow[lane + 32*j] * z1s[lane + 32*j];
#pragma unroll
            for (int o = 16; o; o >>= 1) a += __shfl_xor_sync(~0u, a, o);
            if (lane == 0) h1s[h] = fmaxf(a, 0.f);
        }
        __syncthreads();
        for (int it = 0; it < 16; ++it) {       // z2
            int dd = it * 8 + wid;
            float a = 0.f;
            const float* wrow = W2_1 + dd * 256;
#pragma unroll
            for (int j = 0; j < 8; ++j) a += wrow[lane + 32*j] * h1s[lane + 32*j];
#pragma unroll
            for (int o = 16; o; o >>= 1) a += __shfl_xor_sync(~0u, a, o);
            if (lane == 0) z2s[dd] = z1s[dd] + a;
        }
        __syncthreads();
        float p = 0.f;
        if (t < 128) { float zf = z2s[t] + xh[t]; p = zf*zf - 2.f*xv[t]*zf; }
#pragma unroll
        for (int o = 16; o; o >>= 1) p += __shfl_xor_sync(~0u, p, o);
        if (lane == 0) red[wid] = p;
        __syncthreads();
        if (t == 0) {
            float dv = red[0] + red[1] + red[2] + red[3];
            if (dv < bestd || (dv == bestd && k < bestk)) { bestd = dv; bestk = k; }
        }
        __syncthreads();
    }
    int kwin = bestk;
    if (t == 0) {
        g_code[b] = kwin;
        out[OUT_CODES + b * M_ + m + 1] = (float)kwin;
    }
    g_h0w[b * H_ + t] = fmaxf(g_P1[((m << 8) + kwin) * H_ + t] + g_Q1[b * H_ + t], 0.f);
}

// ---- winner recompute chain (exact fp32, 64-row tiles) ----
__global__ void __launch_bounds__(256) kw_g2(const float* __restrict__ W2, int m) {
    __shared__ float As[2][8][64], Bs[2][8][128];
    float acc[8][8];
    gemm_accR<64, 256, 256>(g_h0w, W2 + 2 * m * 32768, acc, As, Bs);   // grid (1, 16)
    const int tid = threadIdx.x, cRow = blockIdx.y * 64;
    const int tRow = (tid >> 4) * 4, tCol = (tid & 15) * 8;
#pragma unroll
    for (int i = 0; i < 4; ++i) {
        int b = cRow + tRow + i;
        int k = g_code[b];
#pragma unroll
        for (int j = 0; j < 8; ++j) {
            int c = tCol + j;
            g_z1w[b * D_ + c] = acc[i][j] + g_cbz[(m * K_ + k) * D_ + c] + g_y[b * D_ + c];
        }
    }
}
__global__ void __launch_bounds__(256) kw_g3(const float* __restrict__ W1, int m) {
    __shared__ float As[2][8][64], Bs[2][8][128];
    float acc[8][8];
    gemm_accR<64, 128, 128>(g_z1w, W1 + (2 * m + 1) * 32768, acc, As, Bs);  // grid (2, 16)
    const int tid = threadIdx.x, cRow = blockIdx.y * 64, cCol = blockIdx.x * 128;
    const int tRow = (tid >> 4) * 4, tCol = (tid & 15) * 8;
#pragma unroll
    for (int i = 0; i < 4; ++i)
#pragma unroll
        for (int j = 0; j < 8; ++j)
            g_h1w[(cRow + tRow + i) * H_ + cCol + tCol + j] = fmaxf(acc[i][j], 0.f);
}
// kw_g4 + next-step y/Q1, merged. grid (1, 16).
__global__ void __launch_bounds__(256) kw_g4(const float* __restrict__ Wc,
                                             const float* __restrict__ W2,
                                             float* __restrict__ out, int m, int ping) {
    __shared__ float As[2][8][64], Bs[2][8][128];
    float acc[8][8];
    gemm_accR<64, 256, 256>(g_h1w, W2 + (2 * m + 1) * 32768, acc, As, Bs);
    const float* xin  = ping ? g_xb : g_xa;
    float*       xout = ping ? g_xa : g_xb;
    const int tid = threadIdx.x, cRow = blockIdx.y * 64;
    const int tRow = (tid >> 4) * 4, tCol = (tid & 15) * 8;
#pragma unroll
    for (int i = 0; i < 4; ++i) {
        int b = cRow + tRow + i;
#pragma unroll
        for (int j = 0; j < 8; ++j) {
            int c = tCol + j;
            float v = acc[i][j] + g_z1w[b * D_ + c] + xin[b * D_ + c];
            xout[b * D_ + c] = v;
            out[OUT_SIDE + (m + 1) * SIDE_SZ + b * D_ + c] = v;
            if (m == M_ - 2) out[b * D_ + c] = v;
        }
    }
    if (m >= M_ - 2) return;
    int mn = m + 1;
    __syncthreads();   // xout rows of this block visible block-wide; smem reuse safe
    // next-step y = xhat @ Wx^T (this block's 64 rows; grid.x=0 -> cCol=0, full N=128)
    gemm_accR<64, 128, 256>(xout, Wc + mn * 32768 + 128, acc, As, Bs);
#pragma unroll
    for (int i = 0; i < 4; ++i)
#pragma unroll
        for (int j = 0; j < 8; ++j)
            g_y[(cRow + tRow + i) * D_ + tCol + j] = acc[i][j];
    // next-step Q1 = xhat @ Wq1^T, two column halves
#pragma unroll 1
    for (int nh = 0; nh < 2; ++nh) {
        __syncthreads();
        gemm_accR<64, 128, 128>(xout, g_Wq1 + mn * 32768 + nh * 128 * 128, acc, As, Bs);
#pragma unroll
        for (int i = 0; i < 4; ++i)
#pragma unroll
            for (int j = 0; j < 8; ++j)
                g_Q1[(cRow + tRow + i) * H_ + nh * 128 + tCol + j] = acc[i][j];
    }
}

extern "C" void kernel_launch(void* const* d_in, const int* in_sizes, int n_in,
                              void* d_out, int out_size) {
    const float* x   = (const float*)d_in[0];
    const float* cb0 = (const float*)d_in[1];
    const float* cbs = (const float*)d_in[2];
    const float* Wc  = (const float*)d_in[3];
    const float* bc  = (const float*)d_in[4];
    const float* W1  = (const float*)d_in[5];
    const float* W2  = (const float*)d_in[6];
    float* out = (float*)d_out;

    cudaFuncSetAttribute(k_fused, cudaFuncAttributeMaxDynamicSharedMemorySize, SMEM_F);

    // weight-only precomputes
    k_splitw<<<1792, 256>>>(W1, W2);
    k_wq1<<<(M_ - 1) * K_, 128>>>(Wc, W1);
    k_cbzg<<<dim3(1, 2, 7), 256>>>(cbs, Wc, bc);
    k_p1g<<<dim3(2, 2, 7), 256>>>(W1);
    k_step0<<<BS_, 256>>>(x, cb0, out);
    k_yq<<<dim3(3, 16), 256>>>(Wc, 0, 0);   // initial y/Q1 (xhat in g_xa)

    int ping = 0;   // xhat currently in (ping ? g_xb : g_xa)
    for (int m = 0; m < M_ - 1; ++m) {
        k_fused<<<2048, 256, SMEM_F>>>(x, m, ping);
        k_sel<<<BS_, 256>>>(x, W1, W2, out, m, ping);
        kw_g2<<<dim3(1, 16), 256>>>(W2, m);
        kw_g3<<<dim3(2, 16), 256>>>(W1, m);
        kw_g4<<<dim3(1, 16), 256>>>(Wc, W2, out, m, ping);
        ping ^= 1;
    }
}

// round 17
// speedup vs baseline: 1.3282x; 1.1017x over previous
#include <cuda_runtime.h>
#include <cuda_fp16.h>
#include <stdint.h>

// QINCo: D=128, M=8, K=256, L=2, H=256, BS=1024
namespace {
constexpr int D_  = 128;
constexpr int K_  = 256;
constexpr int M_  = 8;
constexpr int H_  = 256;
constexpr int BS_ = 1024;
constexpr int NR  = BS_ * K_;                   // 262144

constexpr int OUT_CODES = BS_ * D_;             // 131072
constexpr int OUT_SIDE  = OUT_CODES + BS_ * M_; // 139264
constexpr int SIDE_SZ   = BS_ * D_;

constexpr int CH = 10240;                       // one limb chunk: 128 rows * 80B
constexpr int Z0_OFF = 0;
constexpr int H_OFF  = 81920;
constexpr int WS_OFF = 163840;
constexpr int SMEM_F = 204800;

constexpr float TAU   = 1e-2f;
constexpr float INV64 = 1.0f / 64.0f;
}

// ---- device scratch (allocation-free) ----
__device__ __align__(128) float g_cbz[(M_-1) * K_ * D_];
__device__ __align__(128) float g_P1[(M_-1) * K_ * H_];
__device__ __align__(128) float g_Wq1[(M_-1) * H_ * D_];   // W1_0 @ Wx (composite)
__device__ __align__(128) float g_y[BS_ * D_];
__device__ __align__(128) float g_Q1[BS_ * H_];
__device__ __align__(128) float g_xa[BS_ * D_];
__device__ __align__(128) float g_xb[BS_ * D_];
__device__ __align__(128) float g_dist[NR];
// fp16 2-limb weights (pre-scaled x64)
__device__ __align__(128) __half g_w1a[7*32768], g_w1b[7*32768];
__device__ __align__(128) __half g_w2a[14*32768], g_w2b[14*32768];
// winner machinery
__device__ __align__(128) float g_h0w[BS_ * H_];
__device__ __align__(128) float g_z1w[BS_ * D_];
__device__ __align__(128) float g_h1w[BS_ * H_];
__device__ int g_code[BS_];

// ================= helpers =================
__device__ __forceinline__ uint32_t smem_u32(const void* p) {
    uint32_t a;
    asm("{ .reg .u64 t; cvta.to.shared.u64 t, %1; cvt.u32.u64 %0, t; }" : "=r"(a) : "l"(p));
    return a;
}
__device__ __forceinline__ void split2(float a, __half& h, __half& l) {
    h = __float2half_rn(a);
    l = __float2half_rn(a - __half2float(h));
}
__device__ __forceinline__ uint32_t pkh(__half a, __half b) {
    return (uint32_t)__half_as_ushort(a) | ((uint32_t)__half_as_ushort(b) << 16);
}
__device__ __forceinline__ void warp_red2(float& a, float& b) {
#pragma unroll
    for (int o = 16; o; o >>= 1) {
        a += __shfl_xor_sync(0xffffffffu, a, o);
        b += __shfl_xor_sync(0xffffffffu, b, o);
    }
}
__device__ __forceinline__ void mma_f16(float* c, const uint32_t* a, const uint32_t* b) {
    asm volatile("mma.sync.aligned.m16n8k16.row.col.f32.f16.f16.f32 "
        "{%0,%1,%2,%3}, {%4,%5,%6,%7}, {%8,%9}, {%0,%1,%2,%3};"
        : "+f"(c[0]), "+f"(c[1]), "+f"(c[2]), "+f"(c[3])
        : "r"(a[0]), "r"(a[1]), "r"(a[2]), "r"(a[3]), "r"(b[0]), "r"(b[1]));
}
__device__ __forceinline__ void ldm4(uint32_t* r, uint32_t addr) {
    asm volatile("ldmatrix.sync.aligned.m8n8.x4.shared.b16 {%0,%1,%2,%3}, [%4];"
        : "=r"(r[0]), "=r"(r[1]), "=r"(r[2]), "=r"(r[3]) : "r"(addr));
}
__device__ __forceinline__ void cpasync16(uint32_t s, const void* g) {
    asm volatile("cp.async.cg.shared.global [%0], [%1], 16;" :: "r"(s), "l"(g));
}
#define CP_COMMIT() asm volatile("cp.async.commit_group;" ::: "memory")
#define CP_WAIT0()  asm volatile("cp.async.wait_group 0;" ::: "memory")
__device__ __forceinline__ uint64_t dup2(float x) {
    uint64_t r; asm("mov.b64 %0, {%1, %1};" : "=l"(r) : "f"(x)); return r;
}
__device__ __forceinline__ void fma2(uint64_t& d, uint64_t a, uint64_t b) {
    asm("fma.rn.f32x2 %0, %1, %2, %0;" : "+l"(d) : "l"(a), "l"(b));
}
__device__ __forceinline__ float2 u2f(uint64_t v) {
    float2 r; asm("mov.b64 {%0, %1}, %2;" : "=f"(r.x), "=f"(r.y) : "l"(v)); return r;
}

// ================= weight precomputes (once per launch) =================
__global__ void k_splitw(const float* __restrict__ W1, const float* __restrict__ W2) {
    int i = blockIdx.x * 256 + threadIdx.x;
    if (i < 7 * 32768) {
        int mm = i / 32768, r = i % 32768;
        __half h, l;
        split2(64.0f * W1[(mm * 2 + 1) * 32768 + r], h, l);
        g_w1a[i] = h; g_w1b[i] = l;
    }
    if (i < 14 * 32768) {
        __half h, l;
        split2(64.0f * W2[i], h, l);
        g_w2a[i] = h; g_w2b[i] = l;
    }
}
// Wq1[m][h][j] = sum_d W1_0[m][h][d] * Wc[m][d][D+j]
__global__ void k_wq1(const float* __restrict__ Wc, const float* __restrict__ W1) {
    int r = blockIdx.x;          // m*256 + h
    int m = r >> 8, h = r & 255;
    __shared__ float w1row[128];
    int j = threadIdx.x;
    w1row[j] = W1[(m * 2) * 32768 + h * 128 + j];
    __syncthreads();
    float acc = 0.f;
    const float* wc = Wc + m * 32768 + 128 + j;
#pragma unroll 8
    for (int d = 0; d < 128; ++d) acc = fmaf(w1row[d], wc[d * 256], acc);
    g_Wq1[r * 128 + j] = acc;
}

// ================= fused per-step fast path =================
// Phase A uses single-limb A (2 mma passes); phases B/C keep 2-limb A (3 passes).
__global__ void __launch_bounds__(256, 1) k_fused(const float* __restrict__ x,
                                                  int m, int ping) {
    extern __shared__ char sm[];
    uint32_t sb = smem_u32(sm);
    const int tid = threadIdx.x, lane = tid & 31, wid = tid >> 5;
    const int wr = (wid >> 2) * 64;
    const int wcn = wid & 3, wc = wcn * 32;
    const int g4 = lane >> 2, q2 = (lane & 3) * 2;
    const int bx = blockIdx.x;
    const int b = bx >> 1, k0 = (bx & 1) * 128;

    float z2[4][4][4] = {};
    float ar[16];

    // 3-pass chunk (A 2 limbs, B 2 limbs)
    auto mma_chunk = [&](float acc[4][4][4], uint32_t aB0, uint32_t aB1,
                         uint32_t bB0, uint32_t bB1) {
#pragma unroll
        for (int h16 = 0; h16 < 2; ++h16) {
            const int kb = h16 * 32;
            uint32_t aF[2][4][4], bF[2][4][2];
#pragma unroll
            for (int limb = 0; limb < 2; ++limb) {
                uint32_t aB = limb ? aB1 : aB0;
                uint32_t bB = limb ? bB1 : bB0;
#pragma unroll
                for (int mt = 0; mt < 4; ++mt)
                    ldm4(aF[limb][mt], aB + (wr + mt*16 + (lane & 15))*80 + kb + (lane >> 4)*16);
#pragma unroll
                for (int p = 0; p < 2; ++p) {
                    uint32_t r[4];
                    ldm4(r, bB + (wc + p*16 + (lane & 7) + ((lane >> 4) & 1)*8)*80 + kb + ((lane >> 3) & 1)*16);
                    bF[limb][p*2  ][0] = r[0]; bF[limb][p*2  ][1] = r[1];
                    bF[limb][p*2+1][0] = r[2]; bF[limb][p*2+1][1] = r[3];
                }
            }
#pragma unroll
            for (int mt = 0; mt < 4; ++mt)
#pragma unroll
                for (int nt = 0; nt < 4; ++nt) {
                    mma_f16(acc[mt][nt], aF[0][mt], bF[0][nt]);
                    mma_f16(acc[mt][nt], aF[0][mt], bF[1][nt]);
                    mma_f16(acc[mt][nt], aF[1][mt], bF[0][nt]);
                }
        }
    };
    // 2-pass chunk (A single limb, B 2 limbs): result = ah*(bh+bl), residual al*b ~2^-11
    auto mma_chunkA = [&](float acc[4][4][4], uint32_t aB0,
                          uint32_t bB0, uint32_t bB1) {
#pragma unroll
        for (int h16 = 0; h16 < 2; ++h16) {
            const int kb = h16 * 32;
            uint32_t aF[4][4], bF[2][4][2];
#pragma unroll
            for (int mt = 0; mt < 4; ++mt)
                ldm4(aF[mt], aB0 + (wr + mt*16 + (lane & 15))*80 + kb + (lane >> 4)*16);
#pragma unroll
            for (int limb = 0; limb < 2; ++limb) {
                uint32_t bB = limb ? bB1 : bB0;
#pragma unroll
                for (int p = 0; p < 2; ++p) {
                    uint32_t r[4];
                    ldm4(r, bB + (wc + p*16 + (lane & 7) + ((lane >> 4) & 1)*8)*80 + kb + ((lane >> 3) & 1)*16);
                    bF[limb][p*2  ][0] = r[0]; bF[limb][p*2  ][1] = r[1];
                    bF[limb][p*2+1][0] = r[2]; bF[limb][p*2+1][1] = r[3];
                }
            }
#pragma unroll
            for (int mt = 0; mt < 4; ++mt)
#pragma unroll
                for (int nt = 0; nt < 4; ++nt) {
                    mma_f16(acc[mt][nt], aF[mt], bF[0][nt]);
                    mma_f16(acc[mt][nt], aF[mt], bF[1][nt]);
                }
        }
    };
    auto cpW = [&](const __half* Wh, const __half* Wl, int stride, int colOff, int buf) {
#pragma unroll
        for (int limb = 0; limb < 2; ++limb) {
            const __half* src = limb ? Wl : Wh;
#pragma unroll
            for (int i = 0; i < 2; ++i) {
                int r2 = tid + 256*i, row = r2 >> 2, cq = r2 & 3;
                cpasync16(sb + WS_OFF + (buf*2 + limb)*CH + row*80 + cq*16,
                          src + row*stride + colOff + cq*8);
            }
        }
    };
    auto ldgA = [&](int ch) {
#pragma unroll
        for (int i = 0; i < 4; ++i) {
            int idx = tid + 256*i, row = idx >> 3, q = idx & 7;
            int kk = k0 + row;
            float4 p  = *(const float4*)(g_P1 + ((m << 8) + kk)*H_ + ch*32 + q*4);
            float4 qq = *(const float4*)(g_Q1 + b*H_ + ch*32 + q*4);
            ar[i*4+0] = fmaxf(p.x + qq.x, 0.f);
            ar[i*4+1] = fmaxf(p.y + qq.y, 0.f);
            ar[i*4+2] = fmaxf(p.z + qq.z, 0.f);
            ar[i*4+3] = fmaxf(p.w + qq.w, 0.f);
        }
    };
    // phase A: store only high limb of A
    auto stsA = [&](int buf) {
#pragma unroll
        for (int i = 0; i < 4; ++i) {
            int idx = tid + 256*i, row = idx >> 3, q = idx & 7;
            __half hh[4];
#pragma unroll
            for (int j = 0; j < 4; ++j) hh[j] = __float2half_rn(ar[i*4+j]);
            char* base = sm + H_OFF + (buf*2)*CH + row*80 + q*8;
            *(uint2*)(base) = make_uint2(pkh(hh[0],hh[1]), pkh(hh[2],hh[3]));
        }
    };

    // ---- phase A (2-pass, single-limb A) ----
    {
        float za[4][4][4] = {};
        const __half* WA = g_w2a + 2*m*32768;
        const __half* WB = g_w2b + 2*m*32768;
        ldgA(0);
        cpW(WA, WB, 256, 0, 0);
        CP_COMMIT();
        stsA(0);
        CP_WAIT0();
        __syncthreads();
        int buf = 0;
#pragma unroll 1
        for (int ch = 0; ch < 8; ++ch) {
            if (ch + 1 < 8) {
                ldgA(ch + 1);
                cpW(WA, WB, 256, (ch + 1)*32, buf ^ 1);
                CP_COMMIT();
            }
            mma_chunkA(za, sb + H_OFF + (buf*2)*CH,
                           sb + WS_OFF + (buf*2)*CH, sb + WS_OFF + (buf*2+1)*CH);
            if (ch + 1 < 8) {
                stsA(buf ^ 1);
                CP_WAIT0();
                __syncthreads();
                buf ^= 1;
            }
        }
        __syncthreads();
#pragma unroll
        for (int mt = 0; mt < 4; ++mt)
#pragma unroll
            for (int half = 0; half < 2; ++half) {
                int row = wr + mt*16 + g4 + half*8;
#pragma unroll
                for (int nt = 0; nt < 4; ++nt) {
                    int col = wc + nt*8 + q2;
                    float2 cz = *(const float2*)(g_cbz + ((m << 8) + k0 + row)*D_ + col);
                    float2 yy = *(const float2*)(g_y + b*D_ + col);
                    float v0 = za[mt][nt][half*2]   * INV64 + cz.x + yy.x;
                    float v1 = za[mt][nt][half*2+1] * INV64 + cz.y + yy.y;
                    __half h0, l0, h1, l1;
                    split2(v0, h0, l0); split2(v1, h1, l1);
                    uint32_t off = (uint32_t)(((col >> 5)*2)*CH + row*80 + (col & 31)*2);
                    *(uint32_t*)(sm + Z0_OFF + off)      = pkh(h0, h1);
                    *(uint32_t*)(sm + Z0_OFF + off + CH) = pkh(l0, l1);
                }
            }
        __syncthreads();
    }

    // ---- phases B/C per 128-col half (3-pass) ----
#pragma unroll 1
    for (int nh = 0; nh < 2; ++nh) {
        {
            float ha[4][4][4] = {};
            const __half* WA = g_w1a + m*32768 + nh*128*128;
            const __half* WB = g_w1b + m*32768 + nh*128*128;
            cpW(WA, WB, 128, 0, 0);
            CP_COMMIT(); CP_WAIT0(); __syncthreads();
            int buf = 0;
#pragma unroll 1
            for (int ch = 0; ch < 4; ++ch) {
                if (ch + 1 < 4) {
                    cpW(WA, WB, 128, (ch + 1)*32, buf ^ 1);
                    CP_COMMIT();
                }
                mma_chunk(ha, sb + Z0_OFF + (ch*2)*CH, sb + Z0_OFF + (ch*2+1)*CH,
                              sb + WS_OFF + (buf*2)*CH, sb + WS_OFF + (buf*2+1)*CH);
                if (ch + 1 < 4) {
                    CP_WAIT0(); __syncthreads(); buf ^= 1;
                }
            }
            __syncthreads();
#pragma unroll
            for (int mt = 0; mt < 4; ++mt)
#pragma unroll
                for (int half = 0; half < 2; ++half) {
                    int row = wr + mt*16 + g4 + half*8;
#pragma unroll
                    for (int nt = 0; nt < 4; ++nt) {
                        int col = wc + nt*8 + q2;
                        float v0 = fmaxf(ha[mt][nt][half*2]   * INV64, 0.f);
                        float v1 = fmaxf(ha[mt][nt][half*2+1] * INV64, 0.f);
                        __half h0, l0, h1, l1;
                        split2(v0, h0, l0); split2(v1, h1, l1);
                        uint32_t off = (uint32_t)(((col >> 5)*2)*CH + row*80 + (col & 31)*2);
                        *(uint32_t*)(sm + H_OFF + off)      = pkh(h0, h1);
                        *(uint32_t*)(sm + H_OFF + off + CH) = pkh(l0, l1);
                    }
                }
            __syncthreads();
        }
        {
            const __half* WA = g_w2a + (2*m + 1)*32768;
            const __half* WB = g_w2b + (2*m + 1)*32768;
            cpW(WA, WB, 256, nh*128, 0);
            CP_COMMIT(); CP_WAIT0(); __syncthreads();
            int buf = 0;
#pragma unroll 1
            for (int ch = 0; ch < 4; ++ch) {
                if (ch + 1 < 4) {
                    cpW(WA, WB, 256, nh*128 + (ch + 1)*32, buf ^ 1);
                    CP_COMMIT();
                }
                mma_chunk(z2, sb + H_OFF + (ch*2)*CH, sb + H_OFF + (ch*2+1)*CH,
                              sb + WS_OFF + (buf*2)*CH, sb + WS_OFF + (buf*2+1)*CH);
                if (ch + 1 < 4) {
                    CP_WAIT0(); __syncthreads(); buf ^= 1;
                }
            }
            __syncthreads();
        }
    }

    // ---- dist epilogue ----
    const float* xin = ping ? g_xb : g_xa;
    float p8[8];
#pragma unroll
    for (int mt = 0; mt < 4; ++mt)
#pragma unroll
        for (int half = 0; half < 2; ++half) {
            int row = wr + mt*16 + g4 + half*8;
            float p = 0.f;
#pragma unroll
            for (int nt = 0; nt < 4; ++nt) {
                int col = wc + nt*8 + q2;
                uint32_t off = (uint32_t)(((col >> 5)*2)*CH + row*80 + (col & 31)*2);
                uint32_t u0 = *(const uint32_t*)(sm + Z0_OFF + off);
                uint32_t u1 = *(const uint32_t*)(sm + Z0_OFF + off + CH);
                float z0a = __half2float(__ushort_as_half((unsigned short)(u0 & 0xffff)))
                          + __half2float(__ushort_as_half((unsigned short)(u1 & 0xffff)));
                float z0b = __half2float(__ushort_as_half((unsigned short)(u0 >> 16)))
                          + __half2float(__ushort_as_half((unsigned short)(u1 >> 16)));
                float2 xh = *(const float2*)(xin + b*D_ + col);
                float2 xv = *(const float2*)(x + b*D_ + col);
                float zf0 = z0a + z2[mt][nt][half*2]   * INV64 + xh.x;
                float zf1 = z0b + z2[mt][nt][half*2+1] * INV64 + xh.y;
                p += zf0 * (zf0 - 2.f*xv.x) + zf1 * (zf1 - 2.f*xv.y);
            }
            p8[mt*2 + half] = p;
        }
#pragma unroll
    for (int j = 0; j < 8; ++j) {
        p8[j] += __shfl_xor_sync(0xffffffffu, p8[j], 1);
        p8[j] += __shfl_xor_sync(0xffffffffu, p8[j], 2);
    }
    float* sd = (float*)(sm + WS_OFF);
    if ((lane & 3) == 0) {
#pragma unroll
        for (int mt = 0; mt < 4; ++mt)
#pragma unroll
            for (int half = 0; half < 2; ++half)
                sd[(wr + mt*16 + g4 + half*8)*4 + wcn] = p8[mt*2 + half];
    }
    __syncthreads();
    if (tid < 128) {
        float s = sd[tid*4] + sd[tid*4+1] + sd[tid*4+2] + sd[tid*4+3];
        g_dist[bx*128 + tid] = s;
    }
}

// ================= f32x2 exact SGEMM core, templated on tile rows ==================
template <int ROWS, int K, int WS>
__device__ __forceinline__ void gemm_accR(const float* __restrict__ A,
                                          const float* __restrict__ W,
                                          float out[8][8],
                                          float (&As)[2][8][ROWS],
                                          float (&Bs)[2][8][128]) {
    constexpr int MR = ROWS / 16;                 // 8 or 4 micro rows
    const int tid  = threadIdx.x;
    const int cRow = blockIdx.y * ROWS;
    const int cCol = blockIdx.x * 128;
    const int tRow = (tid >> 4) * MR;
    const int tCol = (tid & 15) * 8;
    const int rA = tid >> 1;
    const int cA = (tid & 1) * 4;
    const bool aAct = (ROWS == 128) || (tid < ROWS * 2);

    uint64_t acc2[8][4] = {};
    const float* Ap = A + (cRow + (aAct ? rA : 0)) * K + cA;
    const float* Wp = W + (cCol + rA) * WS + cA;

    float4 a4 = make_float4(0.f, 0.f, 0.f, 0.f);
    if (aAct) a4 = *(const float4*)Ap;
    float4 b4 = *(const float4*)Wp;
    if (aAct) {
        As[0][cA+0][rA]=a4.x; As[0][cA+1][rA]=a4.y; As[0][cA+2][rA]=a4.z; As[0][cA+3][rA]=a4.w;
    }
    Bs[0][cA+0][rA]=b4.x; Bs[0][cA+1][rA]=b4.y; Bs[0][cA+2][rA]=b4.z; Bs[0][cA+3][rA]=b4.w;
    __syncthreads();

    constexpr int NT = K / 8;
    int buf = 0;
#pragma unroll 1
    for (int it = 0; it < NT; ++it) {
        float4 an = make_float4(0.f, 0.f, 0.f, 0.f), bn;
        if (it + 1 < NT) {
            if (aAct) an = *(const float4*)(Ap + (it + 1) * 8);
            bn = *(const float4*)(Wp + (it + 1) * 8);
        }
#pragma unroll
        for (int kk = 0; kk < 8; ++kk) {
            float rm[MR];
#pragma unroll
            for (int r = 0; r < MR; r += 4)
                *(float4*)(rm + r) = *(const float4*)&As[buf][kk][tRow + r];
            uint64_t rn2[4];
            *(uint4*)(&rn2[0]) = *(const uint4*)&Bs[buf][kk][tCol];
            *(uint4*)(&rn2[2]) = *(const uint4*)&Bs[buf][kk][tCol+4];
#pragma unroll
            for (int i = 0; i < MR; ++i) {
                uint64_t am = dup2(rm[i]);
#pragma unroll
                for (int j = 0; j < 4; ++j) fma2(acc2[i][j], am, rn2[j]);
            }
        }
        if (it + 1 < NT) {
            int nb = buf ^ 1;
            if (aAct) {
                As[nb][cA+0][rA]=an.x; As[nb][cA+1][rA]=an.y; As[nb][cA+2][rA]=an.z; As[nb][cA+3][rA]=an.w;
            }
            Bs[nb][cA+0][rA]=bn.x; Bs[nb][cA+1][rA]=bn.y; Bs[nb][cA+2][rA]=bn.z; Bs[nb][cA+3][rA]=bn.w;
            __syncthreads();
            buf = nb;
        }
    }
#pragma unroll
    for (int i = 0; i < MR; ++i)
#pragma unroll
        for (int j = 0; j < 4; ++j) {
            float2 t = u2f(acc2[i][j]);
            out[i][2*j] = t.x; out[i][2*j+1] = t.y;
        }
}

// ---- setup GEMMs (exact fp32, 128-row tiles, one-time) ----
__global__ void __launch_bounds__(256) k_cbzg(const float* __restrict__ cbs,
                                              const float* __restrict__ Wc,
                                              const float* __restrict__ bc) {
    __shared__ float As[2][8][128], Bs[2][8][128];
    int m = blockIdx.z;   // grid (1, 2, 7)
    float acc[8][8];
    const float* A = cbs + m * K_ * D_;
    gemm_accR<128, 128, 256>(A, Wc + m * D_ * 2 * D_, acc, As, Bs);
    const int tid = threadIdx.x, cRow = blockIdx.y * 128;
    const int tRow = (tid >> 4) * 8, tCol = (tid & 15) * 8;
#pragma unroll
    for (int i = 0; i < 8; ++i)
#pragma unroll
        for (int j = 0; j < 8; ++j) {
            int r = cRow + tRow + i, c = tCol + j;
            g_cbz[(m * K_ + r) * D_ + c] = acc[i][j] + A[r * D_ + c] + bc[m * D_ + c];
        }
}
__global__ void __launch_bounds__(256) k_p1g(const float* __restrict__ W1) {
    __shared__ float As[2][8][128], Bs[2][8][128];
    int m = blockIdx.z;   // grid (2, 2, 7)
    float acc[8][8];
    gemm_accR<128, 128, 128>(g_cbz + m * K_ * D_, W1 + (m * 2) * H_ * D_, acc, As, Bs);
    const int tid = threadIdx.x, cRow = blockIdx.y * 128, cCol = blockIdx.x * 128;
    const int tRow = (tid >> 4) * 8, tCol = (tid & 15) * 8;
#pragma unroll
    for (int i = 0; i < 8; ++i)
#pragma unroll
        for (int j = 0; j < 8; ++j)
            g_P1[(m * K_ + cRow + tRow + i) * H_ + cCol + tCol + j] = acc[i][j];
}
// next-step y AND Q1, 64-row tiles, grid (3, 16)
__global__ void __launch_bounds__(256) k_yq(const float* __restrict__ Wc, int mn, int ping) {
    __shared__ float As[2][8][64], Bs[2][8][128];
    const float* src = ping ? g_xb : g_xa;
    const int bx = blockIdx.x;
    float acc[8][8];
    const int tid = threadIdx.x, cRow = blockIdx.y * 64;
    const int tRow = (tid >> 4) * 4, tCol = (tid & 15) * 8;
    if (bx == 0) {
        gemm_accR<64, 128, 256>(src, Wc + mn * 32768 + 128, acc, As, Bs);
#pragma unroll
        for (int i = 0; i < 4; ++i)
#pragma unroll
            for (int j = 0; j < 8; ++j)
                g_y[(cRow + tRow + i) * D_ + tCol + j] = acc[i][j];
    } else {
        gemm_accR<64, 128, 128>(src, g_Wq1 + mn * 32768 - 16384, acc, As, Bs);
        const int cCol = (bx - 1) * 128;
#pragma unroll
        for (int i = 0; i < 4; ++i)
#pragma unroll
            for (int j = 0; j < 8; ++j)
                g_Q1[(cRow + tRow + i) * H_ + cCol + tCol + j] = acc[i][j];
    }
}

// ================= step 0 (exact fp32) =================
__global__ void k_step0(const float* __restrict__ x, const float* __restrict__ cb0,
                        float* __restrict__ out) {
    int b = blockIdx.x, t = threadIdx.x;
    int w = t >> 5, lane = t & 31;
    __shared__ float4 xs[32];
    __shared__ float  sd[256];
    __shared__ int    si[256];
    if (t < 32) xs[t] = ((const float4*)x)[b * 32 + t];
    __syncthreads();
    float4 xv = xs[lane];
    for (int i = 0; i < 32; ++i) {
        int k = w * 32 + i;
        float4 c = ((const float4*)cb0)[k * 32 + lane];
        float a1 = c.x*c.x + c.y*c.y + c.z*c.z + c.w*c.w;
        float a2 = xv.x*c.x + xv.y*c.y + xv.z*c.z + xv.w*c.w;
        warp_red2(a1, a2);
        if (lane == 0) sd[k] = a1 - 2.f * a2;
    }
    si[t] = t;
    __syncthreads();
    for (int s = 128; s; s >>= 1) {
        if (t < s) {
            float o = sd[t + s]; int oi = si[t + s];
            if (o < sd[t] || (o == sd[t] && oi < si[t])) { sd[t] = o; si[t] = oi; }
        }
        __syncthreads();
    }
    int kb = si[0];
    if (t < D_) {
        float v = cb0[kb * D_ + t];
        g_xa[b * D_ + t] = v;
        out[OUT_SIDE + b * D_ + t] = v;       // side[0]
    }
    if (t == 0) out[OUT_CODES + b * M_] = (float)kb;
}

// ================= merged selection + exact rescue + h0 emit =================
__global__ void k_sel(const float* __restrict__ x, const float* __restrict__ W1,
                      const float* __restrict__ W2, float* __restrict__ out,
                      int m, int ping) {
    int b = blockIdx.x, t = threadIdx.x, lane = t & 31, wid = t >> 5;
    __shared__ float sd[256], sr[256], wk[256];
    __shared__ int   si[256];
    __shared__ int   cnt, clist_s[16];
    __shared__ float xh[128], xv[128], h0s[256], z1s[128], h1s[256], z2s[128];
    __shared__ float red[8], bestd;
    __shared__ int   bestk;

    float d = g_dist[b * 256 + t];
    sd[t] = d; sr[t] = d; si[t] = t;
    if (t == 0) cnt = 0;
    __syncthreads();
    for (int s = 128; s; s >>= 1) {
        if (t < s) {
            float o = sr[t + s]; int oi = si[t + s];
            if (o < sr[t] || (o == sr[t] && oi < si[t])) { sr[t] = o; si[t] = oi; }
        }
        __syncthreads();
    }
    float d1 = sr[0];
    int   kb = si[0];
    if (sd[t] <= d1 + TAU) {
        int pos = atomicAdd(&cnt, 1);
        if (pos < 16) clist_s[pos] = t;
    }
    __syncthreads();
    int C = cnt;
    if (C == 1) {
        if (t == 0) {
            g_code[b] = kb;
            out[OUT_CODES + b * M_ + m + 1] = (float)kb;
        }
        g_h0w[b * H_ + t] = fmaxf(g_P1[((m << 8) + kb) * H_ + t] + g_Q1[b * H_ + t], 0.f);
        return;
    }
    if (C > 16) {   // extract 16 smallest (rare)
        wk[t] = sd[t];
        __syncthreads();
        for (int r = 0; r < 16; ++r) {
            sr[t] = wk[t]; si[t] = t;
            __syncthreads();
            for (int s = 128; s; s >>= 1) {
                if (t < s) {
                    float o = sr[t + s]; int oi = si[t + s];
                    if (o < sr[t] || (o == sr[t] && oi < si[t])) { sr[t] = o; si[t] = oi; }
                }
                __syncthreads();
            }
            if (t == 0) clist_s[r] = si[0];
            if (t == si[0]) wk[t] = 3.4e38f;
            __syncthreads();
        }
        C = 16;
    }
    const float* xin = ping ? g_xb : g_xa;
    if (t < 128) { xh[t] = xin[b * 128 + t]; xv[t] = x[b * 128 + t]; }
    if (t == 0) { bestd = 3.4e38f; bestk = 0x7fffffff; }
    __syncthreads();
    const float* W2_0 = W2 + (2 * m) * 32768;
    const float* W1_1 = W1 + (2 * m + 1) * 32768;
    const float* W2_1 = W2 + (2 * m + 1) * 32768;
    for (int i = 0; i < C; ++i) {
        int k = clist_s[i];
        h0s[t] = fmaxf(g_P1[(m * K_ + k) * H_ + t] + g_Q1[b * H_ + t], 0.f);
        __syncthreads();
        for (int it = 0; it < 16; ++it) {       // z1
            int dd = it * 8 + wid;
            float a = 0.f;
            const float* wrow = W2_0 + dd * 256;
#pragma unroll
            for (int j = 0; j < 8; ++j) a += wrow[lane + 32*j] * h0s[lane + 32*j];
#pragma unroll
            for (int o = 16; o; o >>= 1) a += __shfl_xor_sync(~0u, a, o);
            if (lane == 0) z1s[dd] = g_cbz[(m * K_ + k) * D_ + dd] + g_y[b * D_ + dd] + a;
        }
        __syncthreads();
        for (int it = 0; it < 32; ++it) {       // h1
            int h = it * 8 + wid;
            float a = 0.f;
            const float* wrow = W1_1 + h * 128;
#pragma unroll
            for (int j = 0; j < 4; ++j) a += wrow[lane + 32*j] * z1s[lane + 32*j];
#pragma unroll
            for (int o = 16; o; o >>= 1) a += __shfl_xor_sync(~0u, a, o);
            if (lane == 0) h1s[h] = fmaxf(a, 0.f);
        }
        __syncthreads();
        for (int it = 0; it < 16; ++it) {       // z2
            int dd = it * 8 + wid;
            float a = 0.f;
            const float* wrow = W2_1 + dd * 256;
#pragma unroll
            for (int j = 0; j < 8; ++j) a += wrow[lane + 32*j] * h1s[lane + 32*j];
#pragma unroll
            for (int o = 16; o; o >>= 1) a += __shfl_xor_sync(~0u, a, o);
            if (lane == 0) z2s[dd] = z1s[dd] + a;
        }
        __syncthreads();
        float p = 0.f;
        if (t < 128) { float zf = z2s[t] + xh[t]; p = zf*zf - 2.f*xv[t]*zf; }
#pragma unroll
        for (int o = 16; o; o >>= 1) p += __shfl_xor_sync(~0u, p, o);
        if (lane == 0) red[wid] = p;
        __syncthreads();
        if (t == 0) {
            float dv = red[0] + red[1] + red[2] + red[3];
            if (dv < bestd || (dv == bestd && k < bestk)) { bestd = dv; bestk = k; }
        }
        __syncthreads();
    }
    int kwin = bestk;
    if (t == 0) {
        g_code[b] = kwin;
        out[OUT_CODES + b * M_ + m + 1] = (float)kwin;
    }
    g_h0w[b * H_ + t] = fmaxf(g_P1[((m << 8) + kwin) * H_ + t] + g_Q1[b * H_ + t], 0.f);
}

// ---- winner recompute chain (exact fp32, 64-row tiles) ----
__global__ void __launch_bounds__(256) kw_g2(const float* __restrict__ W2, int m) {
    __shared__ float As[2][8][64], Bs[2][8][128];
    float acc[8][8];
    gemm_accR<64, 256, 256>(g_h0w, W2 + 2 * m * 32768, acc, As, Bs);   // grid (1, 16)
    const int tid = threadIdx.x, cRow = blockIdx.y * 64;
    const int tRow = (tid >> 4) * 4, tCol = (tid & 15) * 8;
#pragma unroll
    for (int i = 0; i < 4; ++i) {
        int b = cRow + tRow + i;
        int k = g_code[b];
#pragma unroll
        for (int j = 0; j < 8; ++j) {
            int c = tCol + j;
            g_z1w[b * D_ + c] = acc[i][j] + g_cbz[(m * K_ + k) * D_ + c] + g_y[b * D_ + c];
        }
    }
}
__global__ void __launch_bounds__(256) kw_g3(const float* __restrict__ W1, int m) {
    __shared__ float As[2][8][64], Bs[2][8][128];
    float acc[8][8];
    gemm_accR<64, 128, 128>(g_z1w, W1 + (2 * m + 1) * 32768, acc, As, Bs);  // grid (2, 16)
    const int tid = threadIdx.x, cRow = blockIdx.y * 64, cCol = blockIdx.x * 128;
    const int tRow = (tid >> 4) * 4, tCol = (tid & 15) * 8;
#pragma unroll
    for (int i = 0; i < 4; ++i)
#pragma unroll
        for (int j = 0; j < 8; ++j)
            g_h1w[(cRow + tRow + i) * H_ + cCol + tCol + j] = fmaxf(acc[i][j], 0.f);
}
__global__ void __launch_bounds__(256) kw_g4(const float* __restrict__ W2,
                                             float* __restrict__ out, int m, int ping) {
    __shared__ float As[2][8][64], Bs[2][8][128];
    float acc[8][8];
    gemm_accR<64, 256, 256>(g_h1w, W2 + (2 * m + 1) * 32768, acc, As, Bs);   // grid (1, 16)
    const float* xin  = ping ? g_xb : g_xa;
    float*       xout = ping ? g_xa : g_xb;
    const int tid = threadIdx.x, cRow = blockIdx.y * 64;
    const int tRow = (tid >> 4) * 4, tCol = (tid & 15) * 8;
#pragma unroll
    for (int i = 0; i < 4; ++i) {
        int b = cRow + tRow + i;
#pragma unroll
        for (int j = 0; j < 8; ++j) {
            int c = tCol + j;
            float v = acc[i][j] + g_z1w[b * D_ + c] + xin[b * D_ + c];
            xout[b * D_ + c] = v;
            out[OUT_SIDE + (m + 1) * SIDE_SZ + b * D_ + c] = v;
            if (m == M_ - 2) out[b * D_ + c] = v;
        }
    }
}

extern "C" void kernel_launch(void* const* d_in, const int* in_sizes, int n_in,
                              void* d_out, int out_size) {
    const float* x   = (const float*)d_in[0];
    const float* cb0 = (const float*)d_in[1];
    const float* cbs = (const float*)d_in[2];
    const float* Wc  = (const float*)d_in[3];
    const float* bc  = (const float*)d_in[4];
    const float* W1  = (const float*)d_in[5];
    const float* W2  = (const float*)d_in[6];
    float* out = (float*)d_out;

    cudaFuncSetAttribute(k_fused, cudaFuncAttributeMaxDynamicSharedMemorySize, SMEM_F);

    // weight-only precomputes
    k_splitw<<<1792, 256>>>(W1, W2);
    k_wq1<<<(M_ - 1) * K_, 128>>>(Wc, W1);
    k_cbzg<<<dim3(1, 2, 7), 256>>>(cbs, Wc, bc);
    k_p1g<<<dim3(2, 2, 7), 256>>>(W1);
    k_step0<<<BS_, 256>>>(x, cb0, out);
    k_yq<<<dim3(3, 16), 256>>>(Wc, 0, 0);   // initial y/Q1 (xhat in g_xa)

    int ping = 0;   // xhat currently in (ping ? g_xb : g_xa)
    for (int m = 0; m < M_ - 1; ++m) {
        k_fused<<<2048, 256, SMEM_F>>>(x, m, ping);
        k_sel<<<BS_, 256>>>(x, W1, W2, out, m, ping);
        kw_g2<<<dim3(1, 16), 256>>>(W2, m);
        kw_g3<<<dim3(2, 16), 256>>>(W1, m);
        kw_g4<<<dim3(1, 16), 256>>>(W2, out, m, ping);
        ping ^= 1;
        if (m + 1 < M_ - 1) k_yq<<<dim3(3, 16), 256>>>(Wc, m + 1, ping);
    }
}